// round 4
// baseline (speedup 1.0000x reference)
#include <cuda_runtime.h>
#include <cuda_bf16.h>

#define D_MODEL 1024
#define HEADS   16
#define DEPTH   64
#define BATCH   4
#define SEQ     2048
#define MROWS   (BATCH * SEQ)   /* 8192 */
#define BH      (BATCH * HEADS) /* 64   */

// ---- static scratch (allocation-free per harness rules) ----
__device__ float Qg[(size_t)BH * SEQ * DEPTH];   // [bh][s][d], tf32-rounded
__device__ float Kg[(size_t)BH * SEQ * DEPTH];
__device__ float Vg[(size_t)BH * SEQ * DEPTH];
__device__ float Og[(size_t)BH * SEQ * DEPTH];   // attention out, tf32-rounded
__device__ float Xr[(size_t)MROWS * D_MODEL];    // x rounded to tf32
__device__ float Wr[(size_t)4 * D_MODEL * D_MODEL]; // wq,wk,wv,wo rounded

// ---------------- helpers ----------------
__device__ __forceinline__ unsigned su(const void* p) {
    return (unsigned)__cvta_generic_to_shared(p);
}
__device__ __forceinline__ void cp16(unsigned d, const void* s) {
    asm volatile("cp.async.cg.shared.global [%0], [%1], 16;" :: "r"(d), "l"(s));
}
__device__ __forceinline__ void cpcommit() { asm volatile("cp.async.commit_group;"); }
__device__ __forceinline__ void cpwait0() { asm volatile("cp.async.wait_group 0;"); }
__device__ __forceinline__ void cpwait1() { asm volatile("cp.async.wait_group 1;"); }
__device__ __forceinline__ void cpwait2() { asm volatile("cp.async.wait_group 2;"); }

__device__ __forceinline__ float tf32r(float x) {
    unsigned u;
    asm("cvt.rna.tf32.f32 %0, %1;" : "=r"(u) : "f"(x));
    return __uint_as_float(u);
}
__device__ __forceinline__ void mma8(float* c, const unsigned* a, const unsigned* b) {
    asm volatile(
        "mma.sync.aligned.m16n8k8.row.col.f32.tf32.tf32.f32 "
        "{%0,%1,%2,%3},{%4,%5,%6,%7},{%8,%9},{%0,%1,%2,%3};"
        : "+f"(c[0]), "+f"(c[1]), "+f"(c[2]), "+f"(c[3])
        : "r"(a[0]), "r"(a[1]), "r"(a[2]), "r"(a[3]), "r"(b[0]), "r"(b[1]));
}

// ---------------- kernel 0a: round x -> tf32 ----------------
__global__ __launch_bounds__(256) void round_x_kernel(
    const float* __restrict__ in, float* __restrict__ out, int n4)
{
    int i = blockIdx.x * 256 + threadIdx.x;
    if (i < n4) {
        float4 v = ((const float4*)in)[i];
        v.x = tf32r(v.x); v.y = tf32r(v.y); v.z = tf32r(v.z); v.w = tf32r(v.w);
        ((float4*)out)[i] = v;
    }
}

// ---------------- kernel 0b: round all 4 weights (one launch) ----------------
__global__ __launch_bounds__(256) void round_w_kernel(
    const float* __restrict__ w0, const float* __restrict__ w1,
    const float* __restrict__ w2, const float* __restrict__ w3,
    float* __restrict__ out, int n4)
{
    const float* src = (blockIdx.y == 0) ? w0 : (blockIdx.y == 1) ? w1
                       : (blockIdx.y == 2) ? w2 : w3;
    float* dst = out + (size_t)blockIdx.y * (size_t)D_MODEL * D_MODEL;
    int i = blockIdx.x * 256 + threadIdx.x;
    if (i < n4) {
        float4 v = ((const float4*)src)[i];
        v.x = tf32r(v.x); v.y = tf32r(v.y); v.z = tf32r(v.z); v.w = tf32r(v.w);
        ((float4*)dst)[i] = v;
    }
}

// ============================================================
// Kernel 1: proj  out_heads = heads(Xr @ Wr + b), tf32 mma
//   CTA 256x128x32, 3-stage cp.async. 8 warps, 64x64 warp tile.
// ============================================================
#define AST 36    /* A smem stride */
#define BST 136   /* B smem stride */
#define ABUF (256 * AST)   /* 9216 floats */
#define BBUF (32 * BST)    /* 4352 floats */

__global__ __launch_bounds__(256, 1) void proj_tc_kernel(
    const float* __restrict__ A, const float* __restrict__ W,
    const float* __restrict__ bias, float* __restrict__ out)
{
    extern __shared__ float sm[];
    float* Asm[3] = { sm, sm + ABUF, sm + 2 * ABUF };
    float* Bsm[3] = { sm + 3 * ABUF, sm + 3 * ABUF + BBUF, sm + 3 * ABUF + 2 * BBUF };

    const int tid = threadIdx.x;
    const int m0 = blockIdx.y * 256, n0 = blockIdx.x * 128;
    const int warp = tid >> 5, lane = tid & 31;
    const int g = lane >> 2, t = lane & 3;
    const int wm = (warp & 3) * 64, wn = (warp >> 2) * 64;

    float acc[4][8][4] = {};

#define PROJ_LOAD(buf, k0)                                                        \
    do {                                                                          \
        _Pragma("unroll")                                                         \
        for (int i = 0; i < 8; i++) {                                             \
            int id = tid + i * 256; int r = id >> 3, cc = id & 7;                 \
            cp16(su(&Asm[buf][r * AST + cc * 4]),                                 \
                 A + (size_t)(m0 + r) * 1024 + (k0) + cc * 4);                    \
        }                                                                         \
        _Pragma("unroll")                                                         \
        for (int i = 0; i < 4; i++) {                                             \
            int id = tid + i * 256; int r = id >> 5, cc = id & 31;                \
            cp16(su(&Bsm[buf][r * BST + cc * 4]),                                 \
                 W + (size_t)((k0) + r) * 1024 + n0 + cc * 4);                    \
        }                                                                         \
        cpcommit();                                                               \
    } while (0)

    PROJ_LOAD(0, 0);
    PROJ_LOAD(1, 32);
    for (int it = 0; it < 32; it++) {
        if (it + 2 < 32) { PROJ_LOAD((it + 2) % 3, (it + 2) * 32); cpwait2(); }
        else if (it + 1 < 32) cpwait1();
        else cpwait0();
        __syncthreads();
        const float* a_s = Asm[it % 3];
        const float* b_s = Bsm[it % 3];
#pragma unroll
        for (int ks = 0; ks < 32; ks += 8) {
            unsigned a[4][4], b[8][2];
#pragma unroll
            for (int ma = 0; ma < 4; ma++) {
                int rb = wm + ma * 16;
                a[ma][0] = __float_as_uint(a_s[(rb + g) * AST + ks + t]);
                a[ma][1] = __float_as_uint(a_s[(rb + g + 8) * AST + ks + t]);
                a[ma][2] = __float_as_uint(a_s[(rb + g) * AST + ks + t + 4]);
                a[ma][3] = __float_as_uint(a_s[(rb + g + 8) * AST + ks + t + 4]);
            }
#pragma unroll
            for (int nb = 0; nb < 8; nb++) {
                b[nb][0] = __float_as_uint(b_s[(ks + t) * BST + wn + nb * 8 + g]);
                b[nb][1] = __float_as_uint(b_s[(ks + t + 4) * BST + wn + nb * 8 + g]);
            }
#pragma unroll
            for (int nb = 0; nb < 8; nb++)
#pragma unroll
                for (int ma = 0; ma < 4; ma++)
                    mma8(acc[ma][nb], a[ma], b[nb]);
        }
        __syncthreads();
    }

    // epilogue: +bias, round to tf32, head transpose [b,s,h*64+d] -> [bh][s][d]
#pragma unroll
    for (int ma = 0; ma < 4; ma++)
#pragma unroll
        for (int nb = 0; nb < 8; nb++) {
            int c0 = n0 + wn + nb * 8 + t * 2;
            float b0 = __ldg(&bias[c0]), b1 = __ldg(&bias[c0 + 1]);
            int h = c0 >> 6, d = c0 & 63;
#pragma unroll
            for (int rr = 0; rr < 2; rr++) {
                int r = m0 + wm + ma * 16 + g + rr * 8;
                int bb = r >> 11, ss = r & 2047;
                float2 v;
                v.x = tf32r(acc[ma][nb][rr * 2 + 0] + b0);
                v.y = tf32r(acc[ma][nb][rr * 2 + 1] + b1);
                *(float2*)&out[(((size_t)(bb * 16 + h)) * 2048 + ss) * 64 + d] = v;
            }
        }
}

// ============================================================
// Kernel 2: FLASH ATTENTION  (unchanged from R3)
// ============================================================
#define QS_STRIDE 68
#define KS_STRIDE 68
#define VS_STRIDE 72

__global__ __launch_bounds__(256, 1) void flash_attn_kernel()
{
    extern __shared__ float sm[];
    float* Qs = sm;                                  // 128 x 68 = 8704
    float* Ks[2] = { sm + 8704, sm + 8704 + 8704 };  // each 128 x 68
    float* Vs[2] = { sm + 26112, sm + 26112 + 9216 }; // each 128 x 72

    const int bh = blockIdx.y;
    const int m0 = blockIdx.x * 128;
    const float* Qp = Qg + (size_t)bh * SEQ * DEPTH;
    const float* Kp = Kg + (size_t)bh * SEQ * DEPTH;
    const float* Vp = Vg + (size_t)bh * SEQ * DEPTH;
    float* Op = Og + (size_t)bh * SEQ * DEPTH;

    const int tid = threadIdx.x;
    const int warp = tid >> 5, lane = tid & 31;
    const int g = lane >> 2, t = lane & 3;
    const int wq0 = warp * 16;
    const unsigned FULL = 0xffffffffu;

#pragma unroll
    for (int i = 0; i < 8; i++) {
        int id = tid + i * 256; int r = id >> 4, c = (id & 15) * 4;
        cp16(su(&Qs[r * QS_STRIDE + c]), Qp + (size_t)(m0 + r) * 64 + c);
    }
    cpcommit();

#define KV_LOAD(buf, kv0)                                                         \
    do {                                                                          \
        _Pragma("unroll")                                                         \
        for (int i = 0; i < 8; i++) {                                             \
            int id = tid + i * 256; int r = id >> 4, c = (id & 15) * 4;           \
            cp16(su(&Ks[buf][r * KS_STRIDE + c]),                                 \
                 Kp + (size_t)((kv0) + r) * 64 + c);                              \
        }                                                                         \
        _Pragma("unroll")                                                         \
        for (int i = 0; i < 8; i++) {                                             \
            int id = tid + i * 256; int r = id >> 4, c = (id & 15) * 4;           \
            cp16(su(&Vs[buf][r * VS_STRIDE + c]),                                 \
                 Vp + (size_t)((kv0) + r) * 64 + c);                              \
        }                                                                         \
        cpcommit();                                                               \
    } while (0)

    KV_LOAD(0, 0);
    cpwait1();
    __syncthreads();

    unsigned aq[8][4];
#pragma unroll
    for (int kb = 0; kb < 8; kb++) {
        aq[kb][0] = __float_as_uint(0.125f * Qs[(wq0 + g) * QS_STRIDE + kb * 8 + t]);
        aq[kb][1] = __float_as_uint(0.125f * Qs[(wq0 + g + 8) * QS_STRIDE + kb * 8 + t]);
        aq[kb][2] = __float_as_uint(0.125f * Qs[(wq0 + g) * QS_STRIDE + kb * 8 + t + 4]);
        aq[kb][3] = __float_as_uint(0.125f * Qs[(wq0 + g + 8) * QS_STRIDE + kb * 8 + t + 4]);
    }

    float m0r = -1e30f, m1r = -1e30f, l0 = 0.f, l1 = 0.f;
    float o[8][4] = {};

    for (int j = 0; j < 16; j++) {
        if (j + 1 < 16) { KV_LOAD((j + 1) & 1, (j + 1) * 128); cpwait1(); }
        else cpwait0();
        __syncthreads();
        const float* ks = Ks[j & 1];
        const float* vs = Vs[j & 1];

        float acc[16][4];
#pragma unroll
        for (int nb = 0; nb < 16; nb++)
#pragma unroll
            for (int i = 0; i < 4; i++) acc[nb][i] = 0.f;

#pragma unroll
        for (int kb = 0; kb < 8; kb++) {
#pragma unroll
            for (int nb = 0; nb < 16; nb++) {
                unsigned b[2];
                b[0] = __float_as_uint(ks[(nb * 8 + g) * KS_STRIDE + kb * 8 + t]);
                b[1] = __float_as_uint(ks[(nb * 8 + g) * KS_STRIDE + kb * 8 + t + 4]);
                mma8(acc[nb], aq[kb], b);
            }
        }

        float mx0 = -1e30f, mx1 = -1e30f;
#pragma unroll
        for (int nb = 0; nb < 16; nb++) {
            mx0 = fmaxf(mx0, fmaxf(acc[nb][0], acc[nb][1]));
            mx1 = fmaxf(mx1, fmaxf(acc[nb][2], acc[nb][3]));
        }
        mx0 = fmaxf(mx0, __shfl_xor_sync(FULL, mx0, 1));
        mx0 = fmaxf(mx0, __shfl_xor_sync(FULL, mx0, 2));
        mx1 = fmaxf(mx1, __shfl_xor_sync(FULL, mx1, 1));
        mx1 = fmaxf(mx1, __shfl_xor_sync(FULL, mx1, 2));

        float mn0 = fmaxf(m0r, mx0), mn1 = fmaxf(m1r, mx1);
        float al0 = __expf(m0r - mn0), al1 = __expf(m1r - mn1);
        m0r = mn0; m1r = mn1;

        float s0 = 0.f, s1 = 0.f;
#pragma unroll
        for (int nb = 0; nb < 16; nb++) {
            float p0 = __expf(acc[nb][0] - mn0);
            float p1 = __expf(acc[nb][1] - mn0);
            float p2 = __expf(acc[nb][2] - mn1);
            float p3 = __expf(acc[nb][3] - mn1);
            s0 += p0 + p1; s1 += p2 + p3;
            acc[nb][0] = tf32r(p0); acc[nb][1] = tf32r(p1);
            acc[nb][2] = tf32r(p2); acc[nb][3] = tf32r(p3);
        }
        s0 += __shfl_xor_sync(FULL, s0, 1);
        s0 += __shfl_xor_sync(FULL, s0, 2);
        s1 += __shfl_xor_sync(FULL, s1, 1);
        s1 += __shfl_xor_sync(FULL, s1, 2);
        l0 = l0 * al0 + s0;
        l1 = l1 * al1 + s1;

#pragma unroll
        for (int nb = 0; nb < 8; nb++) {
            o[nb][0] *= al0; o[nb][1] *= al0;
            o[nb][2] *= al1; o[nb][3] *= al1;
        }

        const int srcA = (lane & ~3) | (t >> 1);
        const int srcB = srcA + 2;
        const bool odd = (t & 1);
#pragma unroll
        for (int kb = 0; kb < 16; kb++) {
            float v0 = __shfl_sync(FULL, acc[kb][0], srcA);
            float v1 = __shfl_sync(FULL, acc[kb][1], srcA);
            float w0 = __shfl_sync(FULL, acc[kb][2], srcA);
            float w1 = __shfl_sync(FULL, acc[kb][3], srcA);
            float x0 = __shfl_sync(FULL, acc[kb][0], srcB);
            float x1 = __shfl_sync(FULL, acc[kb][1], srcB);
            float y0 = __shfl_sync(FULL, acc[kb][2], srcB);
            float y1 = __shfl_sync(FULL, acc[kb][3], srcB);
            unsigned ap[4];
            ap[0] = __float_as_uint(odd ? v1 : v0);
            ap[1] = __float_as_uint(odd ? w1 : w0);
            ap[2] = __float_as_uint(odd ? x1 : x0);
            ap[3] = __float_as_uint(odd ? y1 : y0);
#pragma unroll
            for (int nb = 0; nb < 8; nb++) {
                unsigned b[2];
                b[0] = __float_as_uint(vs[(kb * 8 + t) * VS_STRIDE + nb * 8 + g]);
                b[1] = __float_as_uint(vs[(kb * 8 + t + 4) * VS_STRIDE + nb * 8 + g]);
                mma8(o[nb], ap, b);
            }
        }
        __syncthreads();
    }

    float inv0 = 1.f / l0, inv1 = 1.f / l1;
#pragma unroll
    for (int nb = 0; nb < 8; nb++) {
        int c0 = nb * 8 + t * 2;
        {
            int r = m0 + wq0 + g;
            float2 v;
            v.x = tf32r(o[nb][0] * inv0);
            v.y = tf32r(o[nb][1] * inv0);
            *(float2*)&Op[(size_t)r * 64 + c0] = v;
        }
        {
            int r = m0 + wq0 + g + 8;
            float2 v;
            v.x = tf32r(o[nb][2] * inv1);
            v.y = tf32r(o[nb][3] * inv1);
            *(float2*)&Op[(size_t)r * 64 + c0] = v;
        }
    }
}

// ============================================================
// Kernel 3: out = untranspose(Og) @ wo + bo
//   Same 256x128x32 3-stage structure as proj.
// ============================================================
__global__ __launch_bounds__(256, 1) void outproj_tc_kernel(
    const float* __restrict__ W, const float* __restrict__ bo,
    float* __restrict__ out)
{
    extern __shared__ float sm[];
    float* Asm[3] = { sm, sm + ABUF, sm + 2 * ABUF };
    float* Bsm[3] = { sm + 3 * ABUF, sm + 3 * ABUF + BBUF, sm + 3 * ABUF + 2 * BBUF };

    const int tid = threadIdx.x;
    const int m0 = blockIdx.y * 256, n0 = blockIdx.x * 128;
    const int warp = tid >> 5, lane = tid & 31;
    const int g = lane >> 2, t = lane & 3;
    const int wm = (warp & 3) * 64, wn = (warp >> 2) * 64;

    float acc[4][8][4] = {};

#define OP_LOAD(buf, k0)                                                          \
    do {                                                                          \
        _Pragma("unroll")                                                         \
        for (int i = 0; i < 8; i++) {                                             \
            int id = tid + i * 256; int r = id >> 3, cc = id & 7;                 \
            int m = m0 + r; int k = (k0) + cc * 4;                                \
            const float* src = Og + (((size_t)((m >> 11) * 16 + (k >> 6))) * 2048 \
                                     + (m & 2047)) * 64 + (k & 63);               \
            cp16(su(&Asm[buf][r * AST + cc * 4]), src);                           \
        }                                                                         \
        _Pragma("unroll")                                                         \
        for (int i = 0; i < 4; i++) {                                             \
            int id = tid + i * 256; int r = id >> 5, cc = id & 31;                \
            cp16(su(&Bsm[buf][r * BST + cc * 4]),                                 \
                 W + (size_t)((k0) + r) * 1024 + n0 + cc * 4);                    \
        }                                                                         \
        cpcommit();                                                               \
    } while (0)

    OP_LOAD(0, 0);
    OP_LOAD(1, 32);
    for (int it = 0; it < 32; it++) {
        if (it + 2 < 32) { OP_LOAD((it + 2) % 3, (it + 2) * 32); cpwait2(); }
        else if (it + 1 < 32) cpwait1();
        else cpwait0();
        __syncthreads();
        const float* a_s = Asm[it % 3];
        const float* b_s = Bsm[it % 3];
#pragma unroll
        for (int ks = 0; ks < 32; ks += 8) {
            unsigned a[4][4], b[8][2];
#pragma unroll
            for (int ma = 0; ma < 4; ma++) {
                int rb = wm + ma * 16;
                a[ma][0] = __float_as_uint(a_s[(rb + g) * AST + ks + t]);
                a[ma][1] = __float_as_uint(a_s[(rb + g + 8) * AST + ks + t]);
                a[ma][2] = __float_as_uint(a_s[(rb + g) * AST + ks + t + 4]);
                a[ma][3] = __float_as_uint(a_s[(rb + g + 8) * AST + ks + t + 4]);
            }
#pragma unroll
            for (int nb = 0; nb < 8; nb++) {
                b[nb][0] = __float_as_uint(b_s[(ks + t) * BST + wn + nb * 8 + g]);
                b[nb][1] = __float_as_uint(b_s[(ks + t + 4) * BST + wn + nb * 8 + g]);
            }
#pragma unroll
            for (int nb = 0; nb < 8; nb++)
#pragma unroll
                for (int ma = 0; ma < 4; ma++)
                    mma8(acc[ma][nb], a[ma], b[nb]);
        }
        __syncthreads();
    }

#pragma unroll
    for (int ma = 0; ma < 4; ma++)
#pragma unroll
        for (int nb = 0; nb < 8; nb++) {
            int c0 = n0 + wn + nb * 8 + t * 2;
            float b0 = __ldg(&bo[c0]), b1 = __ldg(&bo[c0 + 1]);
#pragma unroll
            for (int rr = 0; rr < 2; rr++) {
                int r = m0 + wm + ma * 16 + g + rr * 8;
                float2 v;
                v.x = acc[ma][nb][rr * 2 + 0] + b0;
                v.y = acc[ma][nb][rr * 2 + 1] + b1;
                *(float2*)&out[(size_t)r * 1024 + c0] = v;
            }
        }
}

// ============================================================
extern "C" void kernel_launch(void* const* d_in, const int* in_sizes, int n_in,
                              void* d_out, int out_size)
{
    const float* x  = (const float*)d_in[0];
    const float* wq = (const float*)d_in[1];
    const float* bq = (const float*)d_in[2];
    const float* wk = (const float*)d_in[3];
    const float* bk = (const float*)d_in[4];
    const float* wv = (const float*)d_in[5];
    const float* bv = (const float*)d_in[6];
    const float* wo = (const float*)d_in[7];
    const float* bo = (const float*)d_in[8];
    float* out = (float*)d_out;

    const int GEMM_SMEM = (3 * ABUF + 3 * BBUF) * 4;   // 162816 bytes
    cudaFuncSetAttribute(proj_tc_kernel,    cudaFuncAttributeMaxDynamicSharedMemorySize, GEMM_SMEM);
    cudaFuncSetAttribute(flash_attn_kernel, cudaFuncAttributeMaxDynamicSharedMemorySize, 178176);
    cudaFuncSetAttribute(outproj_tc_kernel, cudaFuncAttributeMaxDynamicSharedMemorySize, GEMM_SMEM);

    float* Xr_p; cudaGetSymbolAddress((void**)&Xr_p, Xr);
    float* Wr_p; cudaGetSymbolAddress((void**)&Wr_p, Wr);
    float* Qp;   cudaGetSymbolAddress((void**)&Qp, Qg);
    float* Kp;   cudaGetSymbolAddress((void**)&Kp, Kg);
    float* Vp;   cudaGetSymbolAddress((void**)&Vp, Vg);

    dim3 blk(256);
    const size_t WSZ = (size_t)D_MODEL * D_MODEL;

    // launch 0: round x;  launch 1: round all four weights
    {
        int n4 = (MROWS * D_MODEL) / 4;
        round_x_kernel<<<(n4 + 255) / 256, blk>>>(x, Xr_p, n4);
        int w4 = (int)(WSZ / 4);
        round_w_kernel<<<dim3((w4 + 255) / 256, 4), blk>>>(wq, wk, wv, wo, Wr_p, w4);
    }

    dim3 gproj(D_MODEL / 128, MROWS / 256);  // (8, 32) = 256 CTAs
    proj_tc_kernel<<<gproj, blk, GEMM_SMEM>>>(Xr_p, Wr_p + 0 * WSZ, bq, Qp);
    proj_tc_kernel<<<gproj, blk, GEMM_SMEM>>>(Xr_p, Wr_p + 1 * WSZ, bk, Kp);
    proj_tc_kernel<<<gproj, blk, GEMM_SMEM>>>(Xr_p, Wr_p + 2 * WSZ, bv, Vp);

    flash_attn_kernel<<<dim3(SEQ / 128, BH), blk, 178176>>>();   // launch #5

    outproj_tc_kernel<<<gproj, blk, GEMM_SMEM>>>(Wr_p + 3 * WSZ, bo, out);
}

// round 5
// speedup vs baseline: 1.0395x; 1.0395x over previous
#include <cuda_runtime.h>
#include <cuda_bf16.h>

#define D_MODEL 1024
#define HEADS   16
#define DEPTH   64
#define BATCH   4
#define SEQ     2048
#define MROWS   (BATCH * SEQ)   /* 8192 */
#define BH      (BATCH * HEADS) /* 64   */

// ---- static scratch (allocation-free per harness rules) ----
__device__ float Qg[(size_t)BH * SEQ * DEPTH];   // [bh][s][d]
__device__ float Kg[(size_t)BH * SEQ * DEPTH];
__device__ float Vg[(size_t)BH * SEQ * DEPTH];
__device__ float Og[(size_t)BH * SEQ * DEPTH];   // attention out
__device__ float Xr[(size_t)MROWS * D_MODEL];    // x rounded to tf32
__device__ float Wr[(size_t)4 * D_MODEL * D_MODEL]; // wq,wk,wv,wo rounded

// ---------------- helpers ----------------
__device__ __forceinline__ unsigned su(const void* p) {
    return (unsigned)__cvta_generic_to_shared(p);
}
__device__ __forceinline__ void cp16(unsigned d, const void* s) {
    asm volatile("cp.async.cg.shared.global [%0], [%1], 16;" :: "r"(d), "l"(s));
}
__device__ __forceinline__ void cpcommit() { asm volatile("cp.async.commit_group;"); }
__device__ __forceinline__ void cpwait0() { asm volatile("cp.async.wait_group 0;"); }
__device__ __forceinline__ void cpwait1() { asm volatile("cp.async.wait_group 1;"); }

__device__ __forceinline__ float tf32r(float x) {
    unsigned u;
    asm("cvt.rna.tf32.f32 %0, %1;" : "=r"(u) : "f"(x));
    return __uint_as_float(u);
}
__device__ __forceinline__ float ex2(float x) {
    float r;
    asm("ex2.approx.f32 %0, %1;" : "=f"(r) : "f"(x));
    return r;
}
__device__ __forceinline__ void mma8(float* c, const unsigned* a, const unsigned* b) {
    asm volatile(
        "mma.sync.aligned.m16n8k8.row.col.f32.tf32.tf32.f32 "
        "{%0,%1,%2,%3},{%4,%5,%6,%7},{%8,%9},{%0,%1,%2,%3};"
        : "+f"(c[0]), "+f"(c[1]), "+f"(c[2]), "+f"(c[3])
        : "r"(a[0]), "r"(a[1]), "r"(a[2]), "r"(a[3]), "r"(b[0]), "r"(b[1]));
}

// ---------------- kernel 0a: round x -> tf32 ----------------
__global__ __launch_bounds__(256) void round_x_kernel(
    const float* __restrict__ in, float* __restrict__ out, int n4)
{
    int i = blockIdx.x * 256 + threadIdx.x;
    if (i < n4) {
        float4 v = ((const float4*)in)[i];
        v.x = tf32r(v.x); v.y = tf32r(v.y); v.z = tf32r(v.z); v.w = tf32r(v.w);
        ((float4*)out)[i] = v;
    }
}

// ---------------- kernel 0b: round all 4 weights (one launch) ----------------
__global__ __launch_bounds__(256) void round_w_kernel(
    const float* __restrict__ w0, const float* __restrict__ w1,
    const float* __restrict__ w2, const float* __restrict__ w3,
    float* __restrict__ out, int n4)
{
    const float* src = (blockIdx.y == 0) ? w0 : (blockIdx.y == 1) ? w1
                       : (blockIdx.y == 2) ? w2 : w3;
    float* dst = out + (size_t)blockIdx.y * (size_t)D_MODEL * D_MODEL;
    int i = blockIdx.x * 256 + threadIdx.x;
    if (i < n4) {
        float4 v = ((const float4*)src)[i];
        v.x = tf32r(v.x); v.y = tf32r(v.y); v.z = tf32r(v.z); v.w = tf32r(v.w);
        ((float4*)dst)[i] = v;
    }
}

// ============================================================
// Kernel 1: proj  out_heads = heads(Xr @ Wr + b), tf32 mma
//   CTA 128x128x32, 2-stage cp.async, 8 warps (32x64 warp tile),
//   capped at 128 regs for 2 CTAs/SM.
// ============================================================
__global__ __launch_bounds__(256, 2) void proj_tc_kernel(
    const float* __restrict__ A, const float* __restrict__ W,
    const float* __restrict__ bias, float* __restrict__ out)
{
    extern __shared__ float sm[];
    float* Asm[2] = { sm, sm + 4608 };               // 128 rows x stride 36
    float* Bsm[2] = { sm + 9216, sm + 9216 + 4352 }; // 32 rows x stride 136

    const int tid = threadIdx.x;
    const int m0 = blockIdx.y * 128, n0 = blockIdx.x * 128;
    const int warp = tid >> 5, lane = tid & 31;
    const int g = lane >> 2, t = lane & 3;
    const int wm = (warp & 3) * 32, wn = (warp >> 2) * 64;

    float acc[2][8][4] = {};

#define PROJ_LOAD(buf, k0)                                                        \
    do {                                                                          \
        _Pragma("unroll")                                                         \
        for (int i = 0; i < 4; i++) {                                             \
            int id = tid + i * 256; int r = id >> 3, cc = id & 7;                 \
            cp16(su(&Asm[buf][r * 36 + cc * 4]),                                  \
                 A + (size_t)(m0 + r) * 1024 + (k0) + cc * 4);                    \
        }                                                                         \
        _Pragma("unroll")                                                         \
        for (int i = 0; i < 4; i++) {                                             \
            int id = tid + i * 256; int r = id >> 5, cc = id & 31;                \
            cp16(su(&Bsm[buf][r * 136 + cc * 4]),                                 \
                 W + (size_t)((k0) + r) * 1024 + n0 + cc * 4);                    \
        }                                                                         \
        cpcommit();                                                               \
    } while (0)

    PROJ_LOAD(0, 0);
    for (int it = 0; it < 32; it++) {
        if (it + 1 < 32) { PROJ_LOAD((it + 1) & 1, (it + 1) * 32); cpwait1(); }
        else cpwait0();
        __syncthreads();
        const float* a_s = Asm[it & 1];
        const float* b_s = Bsm[it & 1];
#pragma unroll
        for (int ks = 0; ks < 32; ks += 8) {
            unsigned a[2][4], b[8][2];
#pragma unroll
            for (int ma = 0; ma < 2; ma++) {
                int rb = wm + ma * 16;
                a[ma][0] = __float_as_uint(a_s[(rb + g) * 36 + ks + t]);
                a[ma][1] = __float_as_uint(a_s[(rb + g + 8) * 36 + ks + t]);
                a[ma][2] = __float_as_uint(a_s[(rb + g) * 36 + ks + t + 4]);
                a[ma][3] = __float_as_uint(a_s[(rb + g + 8) * 36 + ks + t + 4]);
            }
#pragma unroll
            for (int nb = 0; nb < 8; nb++) {
                b[nb][0] = __float_as_uint(b_s[(ks + t) * 136 + wn + nb * 8 + g]);
                b[nb][1] = __float_as_uint(b_s[(ks + t + 4) * 136 + wn + nb * 8 + g]);
            }
#pragma unroll
            for (int nb = 0; nb < 8; nb++)
#pragma unroll
                for (int ma = 0; ma < 2; ma++)
                    mma8(acc[ma][nb], a[ma], b[nb]);
        }
        __syncthreads();
    }

    // epilogue: +bias, head transpose (mma consumers truncate to tf32 in HW)
#pragma unroll
    for (int ma = 0; ma < 2; ma++)
#pragma unroll
        for (int nb = 0; nb < 8; nb++) {
            int c0 = n0 + wn + nb * 8 + t * 2;
            float b0 = __ldg(&bias[c0]), b1 = __ldg(&bias[c0 + 1]);
            int h = c0 >> 6, d = c0 & 63;
#pragma unroll
            for (int rr = 0; rr < 2; rr++) {
                int r = m0 + wm + ma * 16 + g + rr * 8;
                int bb = r >> 11, ss = r & 2047;
                float2 v;
                v.x = acc[ma][nb][rr * 2 + 0] + b0;
                v.y = acc[ma][nb][rr * 2 + 1] + b1;
                *(float2*)&out[(((size_t)(bb * 16 + h)) * 2048 + ss) * 64 + d] = v;
            }
        }
}

// ============================================================
// Kernel 2: FLASH ATTENTION (log2-domain softmax, no P cvt)
// ============================================================
#define QS_STRIDE 68
#define KS_STRIDE 68
#define VS_STRIDE 72
#define SCL (0.125f * 1.4426950408889634f)   /* 1/sqrt(64) * log2(e) */

__global__ __launch_bounds__(256, 1) void flash_attn_kernel()
{
    extern __shared__ float sm[];
    float* Qs = sm;                                  // 128 x 68 = 8704
    float* Ks[2] = { sm + 8704, sm + 8704 + 8704 };  // each 128 x 68
    float* Vs[2] = { sm + 26112, sm + 26112 + 9216 }; // each 128 x 72

    const int bh = blockIdx.y;
    const int m0 = blockIdx.x * 128;
    const float* Qp = Qg + (size_t)bh * SEQ * DEPTH;
    const float* Kp = Kg + (size_t)bh * SEQ * DEPTH;
    const float* Vp = Vg + (size_t)bh * SEQ * DEPTH;
    float* Op = Og + (size_t)bh * SEQ * DEPTH;

    const int tid = threadIdx.x;
    const int warp = tid >> 5, lane = tid & 31;
    const int g = lane >> 2, t = lane & 3;
    const int wq0 = warp * 16;
    const unsigned FULL = 0xffffffffu;

#pragma unroll
    for (int i = 0; i < 8; i++) {
        int id = tid + i * 256; int r = id >> 4, c = (id & 15) * 4;
        cp16(su(&Qs[r * QS_STRIDE + c]), Qp + (size_t)(m0 + r) * 64 + c);
    }
    cpcommit();

#define KV_LOAD(buf, kv0)                                                         \
    do {                                                                          \
        _Pragma("unroll")                                                         \
        for (int i = 0; i < 8; i++) {                                             \
            int id = tid + i * 256; int r = id >> 4, c = (id & 15) * 4;           \
            cp16(su(&Ks[buf][r * KS_STRIDE + c]),                                 \
                 Kp + (size_t)((kv0) + r) * 64 + c);                              \
        }                                                                         \
        _Pragma("unroll")                                                         \
        for (int i = 0; i < 8; i++) {                                             \
            int id = tid + i * 256; int r = id >> 4, c = (id & 15) * 4;           \
            cp16(su(&Vs[buf][r * VS_STRIDE + c]),                                 \
                 Vp + (size_t)((kv0) + r) * 64 + c);                              \
        }                                                                         \
        cpcommit();                                                               \
    } while (0)

    KV_LOAD(0, 0);
    cpwait1();
    __syncthreads();

    // Q fragments pre-scaled so scores land in log2 domain
    unsigned aq[8][4];
#pragma unroll
    for (int kb = 0; kb < 8; kb++) {
        aq[kb][0] = __float_as_uint(SCL * Qs[(wq0 + g) * QS_STRIDE + kb * 8 + t]);
        aq[kb][1] = __float_as_uint(SCL * Qs[(wq0 + g + 8) * QS_STRIDE + kb * 8 + t]);
        aq[kb][2] = __float_as_uint(SCL * Qs[(wq0 + g) * QS_STRIDE + kb * 8 + t + 4]);
        aq[kb][3] = __float_as_uint(SCL * Qs[(wq0 + g + 8) * QS_STRIDE + kb * 8 + t + 4]);
    }

    float m0r = -1e30f, m1r = -1e30f, l0 = 0.f, l1 = 0.f;
    float o[8][4] = {};

    for (int j = 0; j < 16; j++) {
        if (j + 1 < 16) { KV_LOAD((j + 1) & 1, (j + 1) * 128); cpwait1(); }
        else cpwait0();
        __syncthreads();
        const float* ks = Ks[j & 1];
        const float* vs = Vs[j & 1];

        float acc[16][4];
#pragma unroll
        for (int nb = 0; nb < 16; nb++)
#pragma unroll
            for (int i = 0; i < 4; i++) acc[nb][i] = 0.f;

#pragma unroll
        for (int kb = 0; kb < 8; kb++) {
#pragma unroll
            for (int nb = 0; nb < 16; nb++) {
                unsigned b[2];
                b[0] = __float_as_uint(ks[(nb * 8 + g) * KS_STRIDE + kb * 8 + t]);
                b[1] = __float_as_uint(ks[(nb * 8 + g) * KS_STRIDE + kb * 8 + t + 4]);
                mma8(acc[nb], aq[kb], b);
            }
        }

        // online softmax in log2 domain (rows g and g+8)
        float mx0 = -1e30f, mx1 = -1e30f;
#pragma unroll
        for (int nb = 0; nb < 16; nb++) {
            mx0 = fmaxf(mx0, fmaxf(acc[nb][0], acc[nb][1]));
            mx1 = fmaxf(mx1, fmaxf(acc[nb][2], acc[nb][3]));
        }
        mx0 = fmaxf(mx0, __shfl_xor_sync(FULL, mx0, 1));
        mx0 = fmaxf(mx0, __shfl_xor_sync(FULL, mx0, 2));
        mx1 = fmaxf(mx1, __shfl_xor_sync(FULL, mx1, 1));
        mx1 = fmaxf(mx1, __shfl_xor_sync(FULL, mx1, 2));

        float mn0 = fmaxf(m0r, mx0), mn1 = fmaxf(m1r, mx1);
        float al0 = ex2(m0r - mn0), al1 = ex2(m1r - mn1);
        m0r = mn0; m1r = mn1;

        float s0 = 0.f, s1 = 0.f;
#pragma unroll
        for (int nb = 0; nb < 16; nb++) {
            float p0 = ex2(acc[nb][0] - mn0);
            float p1 = ex2(acc[nb][1] - mn0);
            float p2 = ex2(acc[nb][2] - mn1);
            float p3 = ex2(acc[nb][3] - mn1);
            s0 += p0 + p1; s1 += p2 + p3;
            acc[nb][0] = p0; acc[nb][1] = p1;
            acc[nb][2] = p2; acc[nb][3] = p3;
        }
        s0 += __shfl_xor_sync(FULL, s0, 1);
        s0 += __shfl_xor_sync(FULL, s0, 2);
        s1 += __shfl_xor_sync(FULL, s1, 1);
        s1 += __shfl_xor_sync(FULL, s1, 2);
        l0 = l0 * al0 + s0;
        l1 = l1 * al1 + s1;

#pragma unroll
        for (int nb = 0; nb < 8; nb++) {
            o[nb][0] *= al0; o[nb][1] *= al0;
            o[nb][2] *= al1; o[nb][3] *= al1;
        }

        // O += P @ V : C-frag -> A-frag via shuffles (HW truncates P to tf32)
        const int srcA = (lane & ~3) | (t >> 1);
        const int srcB = srcA + 2;
        const bool odd = (t & 1);
#pragma unroll
        for (int kb = 0; kb < 16; kb++) {
            float v0 = __shfl_sync(FULL, acc[kb][0], srcA);
            float v1 = __shfl_sync(FULL, acc[kb][1], srcA);
            float w0 = __shfl_sync(FULL, acc[kb][2], srcA);
            float w1 = __shfl_sync(FULL, acc[kb][3], srcA);
            float x0 = __shfl_sync(FULL, acc[kb][0], srcB);
            float x1 = __shfl_sync(FULL, acc[kb][1], srcB);
            float y0 = __shfl_sync(FULL, acc[kb][2], srcB);
            float y1 = __shfl_sync(FULL, acc[kb][3], srcB);
            unsigned ap[4];
            ap[0] = __float_as_uint(odd ? v1 : v0);
            ap[1] = __float_as_uint(odd ? w1 : w0);
            ap[2] = __float_as_uint(odd ? x1 : x0);
            ap[3] = __float_as_uint(odd ? y1 : y0);
#pragma unroll
            for (int nb = 0; nb < 8; nb++) {
                unsigned b[2];
                b[0] = __float_as_uint(vs[(kb * 8 + t) * VS_STRIDE + nb * 8 + g]);
                b[1] = __float_as_uint(vs[(kb * 8 + t + 4) * VS_STRIDE + nb * 8 + g]);
                mma8(o[nb], ap, b);
            }
        }
        __syncthreads();
    }

    float inv0 = 1.f / l0, inv1 = 1.f / l1;
#pragma unroll
    for (int nb = 0; nb < 8; nb++) {
        int c0 = nb * 8 + t * 2;
        {
            int r = m0 + wq0 + g;
            float2 v;
            v.x = o[nb][0] * inv0;
            v.y = o[nb][1] * inv0;
            *(float2*)&Op[(size_t)r * 64 + c0] = v;
        }
        {
            int r = m0 + wq0 + g + 8;
            float2 v;
            v.x = o[nb][2] * inv1;
            v.y = o[nb][3] * inv1;
            *(float2*)&Op[(size_t)r * 64 + c0] = v;
        }
    }
}

// ============================================================
// Kernel 3: out = untranspose(Og) @ wo + bo, tf32 mma
// ============================================================
__global__ __launch_bounds__(256, 2) void outproj_tc_kernel(
    const float* __restrict__ W, const float* __restrict__ bo,
    float* __restrict__ out)
{
    extern __shared__ float sm[];
    float* Asm[2] = { sm, sm + 4608 };
    float* Bsm[2] = { sm + 9216, sm + 9216 + 4352 };

    const int tid = threadIdx.x;
    const int m0 = blockIdx.y * 128, n0 = blockIdx.x * 128;
    const int warp = tid >> 5, lane = tid & 31;
    const int g = lane >> 2, t = lane & 3;
    const int wm = (warp & 3) * 32, wn = (warp >> 2) * 64;

    float acc[2][8][4] = {};

#define OP_LOAD(buf, k0)                                                          \
    do {                                                                          \
        _Pragma("unroll")                                                         \
        for (int i = 0; i < 4; i++) {                                             \
            int id = tid + i * 256; int r = id >> 3, cc = id & 7;                 \
            int m = m0 + r; int k = (k0) + cc * 4;                                \
            const float* src = Og + (((size_t)((m >> 11) * 16 + (k >> 6))) * 2048 \
                                     + (m & 2047)) * 64 + (k & 63);               \
            cp16(su(&Asm[buf][r * 36 + cc * 4]), src);                            \
        }                                                                         \
        _Pragma("unroll")                                                         \
        for (int i = 0; i < 4; i++) {                                             \
            int id = tid + i * 256; int r = id >> 5, cc = id & 31;                \
            cp16(su(&Bsm[buf][r * 136 + cc * 4]),                                 \
                 W + (size_t)((k0) + r) * 1024 + n0 + cc * 4);                    \
        }                                                                         \
        cpcommit();                                                               \
    } while (0)

    OP_LOAD(0, 0);
    for (int it = 0; it < 32; it++) {
        if (it + 1 < 32) { OP_LOAD((it + 1) & 1, (it + 1) * 32); cpwait1(); }
        else cpwait0();
        __syncthreads();
        const float* a_s = Asm[it & 1];
        const float* b_s = Bsm[it & 1];
#pragma unroll
        for (int ks = 0; ks < 32; ks += 8) {
            unsigned a[2][4], b[8][2];
#pragma unroll
            for (int ma = 0; ma < 2; ma++) {
                int rb = wm + ma * 16;
                a[ma][0] = __float_as_uint(a_s[(rb + g) * 36 + ks + t]);
                a[ma][1] = __float_as_uint(a_s[(rb + g + 8) * 36 + ks + t]);
                a[ma][2] = __float_as_uint(a_s[(rb + g) * 36 + ks + t + 4]);
                a[ma][3] = __float_as_uint(a_s[(rb + g + 8) * 36 + ks + t + 4]);
            }
#pragma unroll
            for (int nb = 0; nb < 8; nb++) {
                b[nb][0] = __float_as_uint(b_s[(ks + t) * 136 + wn + nb * 8 + g]);
                b[nb][1] = __float_as_uint(b_s[(ks + t + 4) * 136 + wn + nb * 8 + g]);
            }
#pragma unroll
            for (int nb = 0; nb < 8; nb++)
#pragma unroll
                for (int ma = 0; ma < 2; ma++)
                    mma8(acc[ma][nb], a[ma], b[nb]);
        }
        __syncthreads();
    }

#pragma unroll
    for (int ma = 0; ma < 2; ma++)
#pragma unroll
        for (int nb = 0; nb < 8; nb++) {
            int c0 = n0 + wn + nb * 8 + t * 2;
            float b0 = __ldg(&bo[c0]), b1 = __ldg(&bo[c0 + 1]);
#pragma unroll
            for (int rr = 0; rr < 2; rr++) {
                int r = m0 + wm + ma * 16 + g + rr * 8;
                float2 v;
                v.x = acc[ma][nb][rr * 2 + 0] + b0;
                v.y = acc[ma][nb][rr * 2 + 1] + b1;
                *(float2*)&out[(size_t)r * 1024 + c0] = v;
            }
        }
}

// ============================================================
extern "C" void kernel_launch(void* const* d_in, const int* in_sizes, int n_in,
                              void* d_out, int out_size)
{
    const float* x  = (const float*)d_in[0];
    const float* wq = (const float*)d_in[1];
    const float* bq = (const float*)d_in[2];
    const float* wk = (const float*)d_in[3];
    const float* bk = (const float*)d_in[4];
    const float* wv = (const float*)d_in[5];
    const float* bv = (const float*)d_in[6];
    const float* wo = (const float*)d_in[7];
    const float* bo = (const float*)d_in[8];
    float* out = (float*)d_out;

    cudaFuncSetAttribute(proj_tc_kernel,    cudaFuncAttributeMaxDynamicSharedMemorySize, 71680);
    cudaFuncSetAttribute(flash_attn_kernel, cudaFuncAttributeMaxDynamicSharedMemorySize, 178176);
    cudaFuncSetAttribute(outproj_tc_kernel, cudaFuncAttributeMaxDynamicSharedMemorySize, 71680);

    float* Xr_p; cudaGetSymbolAddress((void**)&Xr_p, Xr);
    float* Wr_p; cudaGetSymbolAddress((void**)&Wr_p, Wr);
    float* Qp;   cudaGetSymbolAddress((void**)&Qp, Qg);
    float* Kp;   cudaGetSymbolAddress((void**)&Kp, Kg);
    float* Vp;   cudaGetSymbolAddress((void**)&Vp, Vg);

    dim3 blk(256);
    const size_t WSZ = (size_t)D_MODEL * D_MODEL;

    {
        int n4 = (MROWS * D_MODEL) / 4;
        round_x_kernel<<<(n4 + 255) / 256, blk>>>(x, Xr_p, n4);
        int w4 = (int)(WSZ / 4);
        round_w_kernel<<<dim3((w4 + 255) / 256, 4), blk>>>(wq, wk, wv, wo, Wr_p, w4);
    }

    dim3 gproj(D_MODEL / 128, MROWS / 128);  // (8, 64) = 512 CTAs
    proj_tc_kernel<<<gproj, blk, 71680>>>(Xr_p, Wr_p + 0 * WSZ, bq, Qp);
    proj_tc_kernel<<<gproj, blk, 71680>>>(Xr_p, Wr_p + 1 * WSZ, bk, Kp);
    proj_tc_kernel<<<gproj, blk, 71680>>>(Xr_p, Wr_p + 2 * WSZ, bv, Vp);

    flash_attn_kernel<<<dim3(SEQ / 128, BH), blk, 178176>>>();

    outproj_tc_kernel<<<gproj, blk, 71680>>>(Wr_p + 3 * WSZ, bo, out);
}

// round 6
// speedup vs baseline: 1.0416x; 1.0020x over previous
#include <cuda_runtime.h>
#include <cuda_bf16.h>

#define D_MODEL 1024
#define HEADS   16
#define DEPTH   64
#define BATCH   4
#define SEQ     2048
#define MROWS   (BATCH * SEQ)   /* 8192 */
#define BH      (BATCH * HEADS) /* 64   */

// ---- static scratch (allocation-free per harness rules) ----
__device__ float Qg[(size_t)BH * SEQ * DEPTH];   // [bh][s][d]
__device__ float Kg[(size_t)BH * SEQ * DEPTH];
__device__ float Vg[(size_t)BH * SEQ * DEPTH];
__device__ float Og[(size_t)BH * SEQ * DEPTH];   // attention out
__device__ float Xr[(size_t)MROWS * D_MODEL];    // x rounded to tf32
__device__ float Wr[(size_t)4 * D_MODEL * D_MODEL]; // wq,wk,wv,wo rounded

// ---------------- helpers ----------------
__device__ __forceinline__ unsigned su(const void* p) {
    return (unsigned)__cvta_generic_to_shared(p);
}
__device__ __forceinline__ void cp16(unsigned d, const void* s) {
    asm volatile("cp.async.cg.shared.global [%0], [%1], 16;" :: "r"(d), "l"(s));
}
__device__ __forceinline__ void cpcommit() { asm volatile("cp.async.commit_group;"); }
__device__ __forceinline__ void cpwait0() { asm volatile("cp.async.wait_group 0;"); }
__device__ __forceinline__ void cpwait1() { asm volatile("cp.async.wait_group 1;"); }

__device__ __forceinline__ float tf32r(float x) {
    unsigned u;
    asm("cvt.rna.tf32.f32 %0, %1;" : "=r"(u) : "f"(x));
    return __uint_as_float(u);
}
__device__ __forceinline__ float ex2(float x) {
    float r;
    asm("ex2.approx.f32 %0, %1;" : "=f"(r) : "f"(x));
    return r;
}
__device__ __forceinline__ void mma8(float* c, const unsigned* a, const unsigned* b) {
    asm volatile(
        "mma.sync.aligned.m16n8k8.row.col.f32.tf32.tf32.f32 "
        "{%0,%1,%2,%3},{%4,%5,%6,%7},{%8,%9},{%0,%1,%2,%3};"
        : "+f"(c[0]), "+f"(c[1]), "+f"(c[2]), "+f"(c[3])
        : "r"(a[0]), "r"(a[1]), "r"(a[2]), "r"(a[3]), "r"(b[0]), "r"(b[1]));
}

// ---------------- kernel 0a: round x -> tf32 ----------------
__global__ __launch_bounds__(256) void round_x_kernel(
    const float* __restrict__ in, float* __restrict__ out, int n4)
{
    int i = blockIdx.x * 256 + threadIdx.x;
    if (i < n4) {
        float4 v = ((const float4*)in)[i];
        v.x = tf32r(v.x); v.y = tf32r(v.y); v.z = tf32r(v.z); v.w = tf32r(v.w);
        ((float4*)out)[i] = v;
    }
}

// ---------------- kernel 0b: round all 4 weights (one launch) ----------------
__global__ __launch_bounds__(256) void round_w_kernel(
    const float* __restrict__ w0, const float* __restrict__ w1,
    const float* __restrict__ w2, const float* __restrict__ w3,
    float* __restrict__ out, int n4)
{
    const float* src = (blockIdx.y == 0) ? w0 : (blockIdx.y == 1) ? w1
                       : (blockIdx.y == 2) ? w2 : w3;
    float* dst = out + (size_t)blockIdx.y * (size_t)D_MODEL * D_MODEL;
    int i = blockIdx.x * 256 + threadIdx.x;
    if (i < n4) {
        float4 v = ((const float4*)src)[i];
        v.x = tf32r(v.x); v.y = tf32r(v.y); v.z = tf32r(v.z); v.w = tf32r(v.w);
        ((float4*)dst)[i] = v;
    }
}

// ============================================================
// Kernel 1: proj  out_heads = heads(Xr @ Wr + b), tf32 mma
//   CTA 128x128x32, 2-stage cp.async, 8 warps (32x64 warp tile)
// ============================================================
__global__ __launch_bounds__(256, 2) void proj_tc_kernel(
    const float* __restrict__ A, const float* __restrict__ W,
    const float* __restrict__ bias, float* __restrict__ out)
{
    extern __shared__ float sm[];
    float* Asm[2] = { sm, sm + 4608 };               // 128 rows x stride 36
    float* Bsm[2] = { sm + 9216, sm + 9216 + 4352 }; // 32 rows x stride 136

    const int tid = threadIdx.x;
    const int m0 = blockIdx.y * 128, n0 = blockIdx.x * 128;
    const int warp = tid >> 5, lane = tid & 31;
    const int g = lane >> 2, t = lane & 3;
    const int wm = (warp & 3) * 32, wn = (warp >> 2) * 64;

    float acc[2][8][4] = {};

#define PROJ_LOAD(buf, k0)                                                        \
    do {                                                                          \
        _Pragma("unroll")                                                         \
        for (int i = 0; i < 4; i++) {                                             \
            int id = tid + i * 256; int r = id >> 3, cc = id & 7;                 \
            cp16(su(&Asm[buf][r * 36 + cc * 4]),                                  \
                 A + (size_t)(m0 + r) * 1024 + (k0) + cc * 4);                    \
        }                                                                         \
        _Pragma("unroll")                                                         \
        for (int i = 0; i < 4; i++) {                                             \
            int id = tid + i * 256; int r = id >> 5, cc = id & 31;                \
            cp16(su(&Bsm[buf][r * 136 + cc * 4]),                                 \
                 W + (size_t)((k0) + r) * 1024 + n0 + cc * 4);                    \
        }                                                                         \
        cpcommit();                                                               \
    } while (0)

    PROJ_LOAD(0, 0);
    for (int it = 0; it < 32; it++) {
        if (it + 1 < 32) { PROJ_LOAD((it + 1) & 1, (it + 1) * 32); cpwait1(); }
        else cpwait0();
        __syncthreads();
        const float* a_s = Asm[it & 1];
        const float* b_s = Bsm[it & 1];
#pragma unroll
        for (int ks = 0; ks < 32; ks += 8) {
            unsigned a[2][4], b[8][2];
#pragma unroll
            for (int ma = 0; ma < 2; ma++) {
                int rb = wm + ma * 16;
                a[ma][0] = __float_as_uint(a_s[(rb + g) * 36 + ks + t]);
                a[ma][1] = __float_as_uint(a_s[(rb + g + 8) * 36 + ks + t]);
                a[ma][2] = __float_as_uint(a_s[(rb + g) * 36 + ks + t + 4]);
                a[ma][3] = __float_as_uint(a_s[(rb + g + 8) * 36 + ks + t + 4]);
            }
#pragma unroll
            for (int nb = 0; nb < 8; nb++) {
                b[nb][0] = __float_as_uint(b_s[(ks + t) * 136 + wn + nb * 8 + g]);
                b[nb][1] = __float_as_uint(b_s[(ks + t + 4) * 136 + wn + nb * 8 + g]);
            }
#pragma unroll
            for (int nb = 0; nb < 8; nb++)
#pragma unroll
                for (int ma = 0; ma < 2; ma++)
                    mma8(acc[ma][nb], a[ma], b[nb]);
        }
        __syncthreads();
    }

    // epilogue: +bias, head transpose
#pragma unroll
    for (int ma = 0; ma < 2; ma++)
#pragma unroll
        for (int nb = 0; nb < 8; nb++) {
            int c0 = n0 + wn + nb * 8 + t * 2;
            float b0 = __ldg(&bias[c0]), b1 = __ldg(&bias[c0 + 1]);
            int h = c0 >> 6, d = c0 & 63;
#pragma unroll
            for (int rr = 0; rr < 2; rr++) {
                int r = m0 + wm + ma * 16 + g + rr * 8;
                int bb = r >> 11, ss = r & 2047;
                float2 v;
                v.x = acc[ma][nb][rr * 2 + 0] + b0;
                v.y = acc[ma][nb][rr * 2 + 1] + b1;
                *(float2*)&out[(((size_t)(bb * 16 + h)) * 2048 + ss) * 64 + d] = v;
            }
        }
}

// ============================================================
// Kernel 2: FLASH ATTENTION — 64-row KV tiles, 2 CTAs/SM
//   smem: Q 128x68 + 2x(K 64x68) + 2x(V 64x72) = 104 KB
// ============================================================
#define QS_STRIDE 68
#define KS_STRIDE 68
#define VS_STRIDE 72
#define SCL (0.125f * 1.4426950408889634f)   /* 1/sqrt(64) * log2(e) */

__global__ __launch_bounds__(256, 2) void flash_attn_kernel()
{
    extern __shared__ float sm[];
    float* Qs = sm;                                   // 128 x 68 = 8704
    float* Ks[2] = { sm + 8704,  sm + 13056 };        // each 64 x 68 = 4352
    float* Vs[2] = { sm + 17408, sm + 22016 };        // each 64 x 72 = 4608

    const int bh = blockIdx.y;
    const int m0 = blockIdx.x * 128;
    const float* Qp = Qg + (size_t)bh * SEQ * DEPTH;
    const float* Kp = Kg + (size_t)bh * SEQ * DEPTH;
    const float* Vp = Vg + (size_t)bh * SEQ * DEPTH;
    float* Op = Og + (size_t)bh * SEQ * DEPTH;

    const int tid = threadIdx.x;
    const int warp = tid >> 5, lane = tid & 31;
    const int g = lane >> 2, t = lane & 3;
    const int wq0 = warp * 16;
    const unsigned FULL = 0xffffffffu;

    // ---- load Q tile (128x64) ----
#pragma unroll
    for (int i = 0; i < 8; i++) {
        int id = tid + i * 256; int r = id >> 4, c = (id & 15) * 4;
        cp16(su(&Qs[r * QS_STRIDE + c]), Qp + (size_t)(m0 + r) * 64 + c);
    }
    cpcommit();

    // ---- 64-row KV tile loads: 4 float4/thread each for K and V ----
#define KV_LOAD(buf, kv0)                                                         \
    do {                                                                          \
        _Pragma("unroll")                                                         \
        for (int i = 0; i < 4; i++) {                                             \
            int id = tid + i * 256; int r = id >> 4, c = (id & 15) * 4;           \
            cp16(su(&Ks[buf][r * KS_STRIDE + c]),                                 \
                 Kp + (size_t)((kv0) + r) * 64 + c);                              \
        }                                                                         \
        _Pragma("unroll")                                                         \
        for (int i = 0; i < 4; i++) {                                             \
            int id = tid + i * 256; int r = id >> 4, c = (id & 15) * 4;           \
            cp16(su(&Vs[buf][r * VS_STRIDE + c]),                                 \
                 Vp + (size_t)((kv0) + r) * 64 + c);                              \
        }                                                                         \
        cpcommit();                                                               \
    } while (0)

    KV_LOAD(0, 0);
    cpwait1();          // Q arrived (tile0 may still be in flight)
    __syncthreads();

    // ---- pre-scale Q in smem by SCL (one-time) ----
#pragma unroll
    for (int i = 0; i < 8; i++) {
        int id = tid + i * 256; int r = id >> 4, c = (id & 15) * 4;
        float4* p = (float4*)&Qs[r * QS_STRIDE + c];
        float4 v = *p;
        v.x *= SCL; v.y *= SCL; v.z *= SCL; v.w *= SCL;
        *p = v;
    }
    __syncthreads();

    float m0r = -1e30f, m1r = -1e30f, l0 = 0.f, l1 = 0.f;
    float o[8][4] = {};

    for (int j = 0; j < 32; j++) {
        if (j + 1 < 32) { KV_LOAD((j + 1) & 1, (j + 1) * 64); cpwait1(); }
        else cpwait0();
        __syncthreads();
        const float* ks = Ks[j & 1];
        const float* vs = Vs[j & 1];

        // ---- S = (Q*scl) K^T : warp tile 16 x 64 ----
        float acc[8][4];
#pragma unroll
        for (int nb = 0; nb < 8; nb++)
#pragma unroll
            for (int i = 0; i < 4; i++) acc[nb][i] = 0.f;

#pragma unroll
        for (int kb = 0; kb < 8; kb++) {
            unsigned a[4];
            a[0] = __float_as_uint(Qs[(wq0 + g) * QS_STRIDE + kb * 8 + t]);
            a[1] = __float_as_uint(Qs[(wq0 + g + 8) * QS_STRIDE + kb * 8 + t]);
            a[2] = __float_as_uint(Qs[(wq0 + g) * QS_STRIDE + kb * 8 + t + 4]);
            a[3] = __float_as_uint(Qs[(wq0 + g + 8) * QS_STRIDE + kb * 8 + t + 4]);
#pragma unroll
            for (int nb = 0; nb < 8; nb++) {
                unsigned b[2];
                b[0] = __float_as_uint(ks[(nb * 8 + g) * KS_STRIDE + kb * 8 + t]);
                b[1] = __float_as_uint(ks[(nb * 8 + g) * KS_STRIDE + kb * 8 + t + 4]);
                mma8(acc[nb], a, b);
            }
        }

        // ---- online softmax in log2 domain (rows g and g+8) ----
        float mx0 = -1e30f, mx1 = -1e30f;
#pragma unroll
        for (int nb = 0; nb < 8; nb++) {
            mx0 = fmaxf(mx0, fmaxf(acc[nb][0], acc[nb][1]));
            mx1 = fmaxf(mx1, fmaxf(acc[nb][2], acc[nb][3]));
        }
        mx0 = fmaxf(mx0, __shfl_xor_sync(FULL, mx0, 1));
        mx0 = fmaxf(mx0, __shfl_xor_sync(FULL, mx0, 2));
        mx1 = fmaxf(mx1, __shfl_xor_sync(FULL, mx1, 1));
        mx1 = fmaxf(mx1, __shfl_xor_sync(FULL, mx1, 2));

        float mn0 = fmaxf(m0r, mx0), mn1 = fmaxf(m1r, mx1);
        float al0 = ex2(m0r - mn0), al1 = ex2(m1r - mn1);
        m0r = mn0; m1r = mn1;

        float s0 = 0.f, s1 = 0.f;
#pragma unroll
        for (int nb = 0; nb < 8; nb++) {
            float p0 = ex2(acc[nb][0] - mn0);
            float p1 = ex2(acc[nb][1] - mn0);
            float p2 = ex2(acc[nb][2] - mn1);
            float p3 = ex2(acc[nb][3] - mn1);
            s0 += p0 + p1; s1 += p2 + p3;
            acc[nb][0] = p0; acc[nb][1] = p1;
            acc[nb][2] = p2; acc[nb][3] = p3;
        }
        s0 += __shfl_xor_sync(FULL, s0, 1);
        s0 += __shfl_xor_sync(FULL, s0, 2);
        s1 += __shfl_xor_sync(FULL, s1, 1);
        s1 += __shfl_xor_sync(FULL, s1, 2);
        l0 = l0 * al0 + s0;
        l1 = l1 * al1 + s1;

#pragma unroll
        for (int nb = 0; nb < 8; nb++) {
            o[nb][0] *= al0; o[nb][1] *= al0;
            o[nb][2] *= al1; o[nb][3] *= al1;
        }

        // ---- O += P @ V : C-frag -> A-frag via shuffles ----
        const int srcA = (lane & ~3) | (t >> 1);
        const int srcB = srcA + 2;
        const bool odd = (t & 1);
#pragma unroll
        for (int kb = 0; kb < 8; kb++) {
            float v0 = __shfl_sync(FULL, acc[kb][0], srcA);
            float v1 = __shfl_sync(FULL, acc[kb][1], srcA);
            float w0 = __shfl_sync(FULL, acc[kb][2], srcA);
            float w1 = __shfl_sync(FULL, acc[kb][3], srcA);
            float x0 = __shfl_sync(FULL, acc[kb][0], srcB);
            float x1 = __shfl_sync(FULL, acc[kb][1], srcB);
            float y0 = __shfl_sync(FULL, acc[kb][2], srcB);
            float y1 = __shfl_sync(FULL, acc[kb][3], srcB);
            unsigned ap[4];
            ap[0] = __float_as_uint(odd ? v1 : v0);
            ap[1] = __float_as_uint(odd ? w1 : w0);
            ap[2] = __float_as_uint(odd ? x1 : x0);
            ap[3] = __float_as_uint(odd ? y1 : y0);
#pragma unroll
            for (int nb = 0; nb < 8; nb++) {
                unsigned b[2];
                b[0] = __float_as_uint(vs[(kb * 8 + t) * VS_STRIDE + nb * 8 + g]);
                b[1] = __float_as_uint(vs[(kb * 8 + t + 4) * VS_STRIDE + nb * 8 + g]);
                mma8(o[nb], ap, b);
            }
        }
        __syncthreads();
    }

    // ---- epilogue ----
    float inv0 = 1.f / l0, inv1 = 1.f / l1;
#pragma unroll
    for (int nb = 0; nb < 8; nb++) {
        int c0 = nb * 8 + t * 2;
        {
            int r = m0 + wq0 + g;
            float2 v;
            v.x = o[nb][0] * inv0;
            v.y = o[nb][1] * inv0;
            *(float2*)&Op[(size_t)r * 64 + c0] = v;
        }
        {
            int r = m0 + wq0 + g + 8;
            float2 v;
            v.x = o[nb][2] * inv1;
            v.y = o[nb][3] * inv1;
            *(float2*)&Op[(size_t)r * 64 + c0] = v;
        }
    }
}

// ============================================================
// Kernel 3: out = untranspose(Og) @ wo + bo, tf32 mma
// ============================================================
__global__ __launch_bounds__(256, 2) void outproj_tc_kernel(
    const float* __restrict__ W, const float* __restrict__ bo,
    float* __restrict__ out)
{
    extern __shared__ float sm[];
    float* Asm[2] = { sm, sm + 4608 };
    float* Bsm[2] = { sm + 9216, sm + 9216 + 4352 };

    const int tid = threadIdx.x;
    const int m0 = blockIdx.y * 128, n0 = blockIdx.x * 128;
    const int warp = tid >> 5, lane = tid & 31;
    const int g = lane >> 2, t = lane & 3;
    const int wm = (warp & 3) * 32, wn = (warp >> 2) * 64;

    float acc[2][8][4] = {};

#define OP_LOAD(buf, k0)                                                          \
    do {                                                                          \
        _Pragma("unroll")                                                         \
        for (int i = 0; i < 4; i++) {                                             \
            int id = tid + i * 256; int r = id >> 3, cc = id & 7;                 \
            int m = m0 + r; int k = (k0) + cc * 4;                                \
            const float* src = Og + (((size_t)((m >> 11) * 16 + (k >> 6))) * 2048 \
                                     + (m & 2047)) * 64 + (k & 63);               \
            cp16(su(&Asm[buf][r * 36 + cc * 4]), src);                            \
        }                                                                         \
        _Pragma("unroll")                                                         \
        for (int i = 0; i < 4; i++) {                                             \
            int id = tid + i * 256; int r = id >> 5, cc = id & 31;                \
            cp16(su(&Bsm[buf][r * 136 + cc * 4]),                                 \
                 W + (size_t)((k0) + r) * 1024 + n0 + cc * 4);                    \
        }                                                                         \
        cpcommit();                                                               \
    } while (0)

    OP_LOAD(0, 0);
    for (int it = 0; it < 32; it++) {
        if (it + 1 < 32) { OP_LOAD((it + 1) & 1, (it + 1) * 32); cpwait1(); }
        else cpwait0();
        __syncthreads();
        const float* a_s = Asm[it & 1];
        const float* b_s = Bsm[it & 1];
#pragma unroll
        for (int ks = 0; ks < 32; ks += 8) {
            unsigned a[2][4], b[8][2];
#pragma unroll
            for (int ma = 0; ma < 2; ma++) {
                int rb = wm + ma * 16;
                a[ma][0] = __float_as_uint(a_s[(rb + g) * 36 + ks + t]);
                a[ma][1] = __float_as_uint(a_s[(rb + g + 8) * 36 + ks + t]);
                a[ma][2] = __float_as_uint(a_s[(rb + g) * 36 + ks + t + 4]);
                a[ma][3] = __float_as_uint(a_s[(rb + g + 8) * 36 + ks + t + 4]);
            }
#pragma unroll
            for (int nb = 0; nb < 8; nb++) {
                b[nb][0] = __float_as_uint(b_s[(ks + t) * 136 + wn + nb * 8 + g]);
                b[nb][1] = __float_as_uint(b_s[(ks + t + 4) * 136 + wn + nb * 8 + g]);
            }
#pragma unroll
            for (int nb = 0; nb < 8; nb++)
#pragma unroll
                for (int ma = 0; ma < 2; ma++)
                    mma8(acc[ma][nb], a[ma], b[nb]);
        }
        __syncthreads();
    }

#pragma unroll
    for (int ma = 0; ma < 2; ma++)
#pragma unroll
        for (int nb = 0; nb < 8; nb++) {
            int c0 = n0 + wn + nb * 8 + t * 2;
            float b0 = __ldg(&bo[c0]), b1 = __ldg(&bo[c0 + 1]);
#pragma unroll
            for (int rr = 0; rr < 2; rr++) {
                int r = m0 + wm + ma * 16 + g + rr * 8;
                float2 v;
                v.x = acc[ma][nb][rr * 2 + 0] + b0;
                v.y = acc[ma][nb][rr * 2 + 1] + b1;
                *(float2*)&out[(size_t)r * 1024 + c0] = v;
            }
        }
}

// ============================================================
extern "C" void kernel_launch(void* const* d_in, const int* in_sizes, int n_in,
                              void* d_out, int out_size)
{
    const float* x  = (const float*)d_in[0];
    const float* wq = (const float*)d_in[1];
    const float* bq = (const float*)d_in[2];
    const float* wk = (const float*)d_in[3];
    const float* bk = (const float*)d_in[4];
    const float* wv = (const float*)d_in[5];
    const float* bv = (const float*)d_in[6];
    const float* wo = (const float*)d_in[7];
    const float* bo = (const float*)d_in[8];
    float* out = (float*)d_out;

    cudaFuncSetAttribute(proj_tc_kernel,    cudaFuncAttributeMaxDynamicSharedMemorySize, 71680);
    cudaFuncSetAttribute(flash_attn_kernel, cudaFuncAttributeMaxDynamicSharedMemorySize, 106496);
    cudaFuncSetAttribute(outproj_tc_kernel, cudaFuncAttributeMaxDynamicSharedMemorySize, 71680);

    float* Xr_p; cudaGetSymbolAddress((void**)&Xr_p, Xr);
    float* Wr_p; cudaGetSymbolAddress((void**)&Wr_p, Wr);
    float* Qp;   cudaGetSymbolAddress((void**)&Qp, Qg);
    float* Kp;   cudaGetSymbolAddress((void**)&Kp, Kg);
    float* Vp;   cudaGetSymbolAddress((void**)&Vp, Vg);

    dim3 blk(256);
    const size_t WSZ = (size_t)D_MODEL * D_MODEL;

    {
        int n4 = (MROWS * D_MODEL) / 4;
        round_x_kernel<<<(n4 + 255) / 256, blk>>>(x, Xr_p, n4);
        int w4 = (int)(WSZ / 4);
        round_w_kernel<<<dim3((w4 + 255) / 256, 4), blk>>>(wq, wk, wv, wo, Wr_p, w4);
    }

    dim3 gproj(D_MODEL / 128, MROWS / 128);  // (8, 64) = 512 CTAs
    proj_tc_kernel<<<gproj, blk, 71680>>>(Xr_p, Wr_p + 0 * WSZ, bq, Qp);
    proj_tc_kernel<<<gproj, blk, 71680>>>(Xr_p, Wr_p + 1 * WSZ, bk, Kp);
    proj_tc_kernel<<<gproj, blk, 71680>>>(Xr_p, Wr_p + 2 * WSZ, bv, Vp);

    flash_attn_kernel<<<dim3(SEQ / 128, BH), blk, 106496>>>();

    outproj_tc_kernel<<<gproj, blk, 71680>>>(Wr_p + 3 * WSZ, bo, out);
}

// round 8
// speedup vs baseline: 1.0610x; 1.0186x over previous
#include <cuda_runtime.h>
#include <cuda_bf16.h>

#define D_MODEL 1024
#define HEADS   16
#define DEPTH   64
#define BATCH   4
#define SEQ     2048
#define MROWS   (BATCH * SEQ)   /* 8192 */
#define BH      (BATCH * HEADS) /* 64   */

// ---- static scratch (allocation-free per harness rules) ----
__device__ float Qg[(size_t)BH * SEQ * DEPTH];   // [bh][s][d]
__device__ float Kg[(size_t)BH * SEQ * DEPTH];
__device__ float Vg[(size_t)BH * SEQ * DEPTH];
__device__ float Og[(size_t)BH * SEQ * DEPTH];   // attention out
__device__ float Xr[(size_t)MROWS * D_MODEL];    // x rounded to tf32
__device__ float Wr[(size_t)4 * D_MODEL * D_MODEL]; // wq,wk,wv,wo rounded

// device-side output pointer table for merged QKV kernel
__device__ float* QKVout[3];

// ---------------- helpers ----------------
__device__ __forceinline__ unsigned su(const void* p) {
    return (unsigned)__cvta_generic_to_shared(p);
}
__device__ __forceinline__ void cp16(unsigned d, const void* s) {
    asm volatile("cp.async.cg.shared.global [%0], [%1], 16;" :: "r"(d), "l"(s));
}
__device__ __forceinline__ void cpcommit() { asm volatile("cp.async.commit_group;"); }
__device__ __forceinline__ void cpwait0() { asm volatile("cp.async.wait_group 0;"); }
__device__ __forceinline__ void cpwait1() { asm volatile("cp.async.wait_group 1;"); }

__device__ __forceinline__ float tf32r(float x) {
    unsigned u;
    asm("cvt.rna.tf32.f32 %0, %1;" : "=r"(u) : "f"(x));
    return __uint_as_float(u);
}
__device__ __forceinline__ float ex2(float x) {
    float r;
    asm("ex2.approx.f32 %0, %1;" : "=f"(r) : "f"(x));
    return r;
}
__device__ __forceinline__ void mma8(float* c, const unsigned* a, const unsigned* b) {
    asm volatile(
        "mma.sync.aligned.m16n8k8.row.col.f32.tf32.tf32.f32 "
        "{%0,%1,%2,%3},{%4,%5,%6,%7},{%8,%9},{%0,%1,%2,%3};"
        : "+f"(c[0]), "+f"(c[1]), "+f"(c[2]), "+f"(c[3])
        : "r"(a[0]), "r"(a[1]), "r"(a[2]), "r"(a[3]), "r"(b[0]), "r"(b[1]));
}

// ---------------- kernel 0a: round x -> tf32 ----------------
__global__ __launch_bounds__(256) void round_x_kernel(
    const float* __restrict__ in, float* __restrict__ out, int n4)
{
    int i = blockIdx.x * 256 + threadIdx.x;
    if (i < n4) {
        float4 v = ((const float4*)in)[i];
        v.x = tf32r(v.x); v.y = tf32r(v.y); v.z = tf32r(v.z); v.w = tf32r(v.w);
        ((float4*)out)[i] = v;
    }
}

// ---------------- kernel 0b: round all 4 weights (one launch) ----------------
__global__ __launch_bounds__(256) void round_w_kernel(
    const float* __restrict__ w0, const float* __restrict__ w1,
    const float* __restrict__ w2, const float* __restrict__ w3,
    float* __restrict__ out, int n4)
{
    const float* src = (blockIdx.y == 0) ? w0 : (blockIdx.y == 1) ? w1
                       : (blockIdx.y == 2) ? w2 : w3;
    float* dst = out + (size_t)blockIdx.y * (size_t)D_MODEL * D_MODEL;
    int i = blockIdx.x * 256 + threadIdx.x;
    if (i < n4) {
        float4 v = ((const float4*)src)[i];
        v.x = tf32r(v.x); v.y = tf32r(v.y); v.z = tf32r(v.z); v.w = tf32r(v.w);
        ((float4*)dst)[i] = v;
    }
}

// ============================================================
// Kernel 1: MERGED QKV proj — grid.z selects {Q,K,V}
//   out_z = heads(Xr @ Wr_z + b_z), tf32 mma
//   CTA 128x128x32, 2-stage cp.async, 8 warps (32x64 warp tile)
// ============================================================
__global__ __launch_bounds__(256, 2) void proj_qkv_kernel(
    const float* __restrict__ A, const float* __restrict__ Wbase,
    const float* __restrict__ bq, const float* __restrict__ bk,
    const float* __restrict__ bv)
{
    extern __shared__ float sm[];
    float* Asm[2] = { sm, sm + 4608 };               // 128 rows x stride 36
    float* Bsm[2] = { sm + 9216, sm + 9216 + 4352 }; // 32 rows x stride 136

    const int z = blockIdx.z;
    const float* W = Wbase + (size_t)z * D_MODEL * D_MODEL;
    const float* bias = (z == 0) ? bq : (z == 1) ? bk : bv;
    float* out = QKVout[z];

    const int tid = threadIdx.x;
    const int m0 = blockIdx.y * 128, n0 = blockIdx.x * 128;
    const int warp = tid >> 5, lane = tid & 31;
    const int g = lane >> 2, t = lane & 3;
    const int wm = (warp & 3) * 32, wn = (warp >> 2) * 64;

    float acc[2][8][4] = {};

#define PROJ_LOAD(buf, k0)                                                        \
    do {                                                                          \
        _Pragma("unroll")                                                         \
        for (int i = 0; i < 4; i++) {                                             \
            int id = tid + i * 256; int r = id >> 3, cc = id & 7;                 \
            cp16(su(&Asm[buf][r * 36 + cc * 4]),                                  \
                 A + (size_t)(m0 + r) * 1024 + (k0) + cc * 4);                    \
        }                                                                         \
        _Pragma("unroll")                                                         \
        for (int i = 0; i < 4; i++) {                                             \
            int id = tid + i * 256; int r = id >> 5, cc = id & 31;                \
            cp16(su(&Bsm[buf][r * 136 + cc * 4]),                                 \
                 W + (size_t)((k0) + r) * 1024 + n0 + cc * 4);                    \
        }                                                                         \
        cpcommit();                                                               \
    } while (0)

    PROJ_LOAD(0, 0);
    for (int it = 0; it < 32; it++) {
        if (it + 1 < 32) { PROJ_LOAD((it + 1) & 1, (it + 1) * 32); cpwait1(); }
        else cpwait0();
        __syncthreads();
        const float* a_s = Asm[it & 1];
        const float* b_s = Bsm[it & 1];
#pragma unroll
        for (int ks = 0; ks < 32; ks += 8) {
            unsigned a[2][4], b[8][2];
#pragma unroll
            for (int ma = 0; ma < 2; ma++) {
                int rb = wm + ma * 16;
                a[ma][0] = __float_as_uint(a_s[(rb + g) * 36 + ks + t]);
                a[ma][1] = __float_as_uint(a_s[(rb + g + 8) * 36 + ks + t]);
                a[ma][2] = __float_as_uint(a_s[(rb + g) * 36 + ks + t + 4]);
                a[ma][3] = __float_as_uint(a_s[(rb + g + 8) * 36 + ks + t + 4]);
            }
#pragma unroll
            for (int nb = 0; nb < 8; nb++) {
                b[nb][0] = __float_as_uint(b_s[(ks + t) * 136 + wn + nb * 8 + g]);
                b[nb][1] = __float_as_uint(b_s[(ks + t + 4) * 136 + wn + nb * 8 + g]);
            }
#pragma unroll
            for (int nb = 0; nb < 8; nb++)
#pragma unroll
                for (int ma = 0; ma < 2; ma++)
                    mma8(acc[ma][nb], a[ma], b[nb]);
        }
        __syncthreads();
    }

    // epilogue: +bias, head transpose [b,s,h*64+d] -> [bh][s][d]
#pragma unroll
    for (int ma = 0; ma < 2; ma++)
#pragma unroll
        for (int nb = 0; nb < 8; nb++) {
            int c0 = n0 + wn + nb * 8 + t * 2;
            float b0 = __ldg(&bias[c0]), b1 = __ldg(&bias[c0 + 1]);
            int h = c0 >> 6, d = c0 & 63;
#pragma unroll
            for (int rr = 0; rr < 2; rr++) {
                int r = m0 + wm + ma * 16 + g + rr * 8;
                int bb = r >> 11, ss = r & 2047;
                float2 v;
                v.x = acc[ma][nb][rr * 2 + 0] + b0;
                v.y = acc[ma][nb][rr * 2 + 1] + b1;
                *(float2*)&out[(((size_t)(bb * 16 + h)) * 2048 + ss) * 64 + d] = v;
            }
        }
}

// ============================================================
// Kernel 2: FLASH ATTENTION — 64-row KV tiles, 2 CTAs/SM
// ============================================================
#define QS_STRIDE 68
#define KS_STRIDE 68
#define VS_STRIDE 72
#define SCL (0.125f * 1.4426950408889634f)   /* 1/sqrt(64) * log2(e) */

__global__ __launch_bounds__(256, 2) void flash_attn_kernel()
{
    extern __shared__ float sm[];
    float* Qs = sm;                                   // 128 x 68 = 8704
    float* Ks[2] = { sm + 8704,  sm + 13056 };        // each 64 x 68 = 4352
    float* Vs[2] = { sm + 17408, sm + 22016 };        // each 64 x 72 = 4608

    const int bh = blockIdx.y;
    const int m0 = blockIdx.x * 128;
    const float* Qp = Qg + (size_t)bh * SEQ * DEPTH;
    const float* Kp = Kg + (size_t)bh * SEQ * DEPTH;
    const float* Vp = Vg + (size_t)bh * SEQ * DEPTH;
    float* Op = Og + (size_t)bh * SEQ * DEPTH;

    const int tid = threadIdx.x;
    const int warp = tid >> 5, lane = tid & 31;
    const int g = lane >> 2, t = lane & 3;
    const int wq0 = warp * 16;
    const unsigned FULL = 0xffffffffu;

#pragma unroll
    for (int i = 0; i < 8; i++) {
        int id = tid + i * 256; int r = id >> 4, c = (id & 15) * 4;
        cp16(su(&Qs[r * QS_STRIDE + c]), Qp + (size_t)(m0 + r) * 64 + c);
    }
    cpcommit();

#define KV_LOAD(buf, kv0)                                                         \
    do {                                                                          \
        _Pragma("unroll")                                                         \
        for (int i = 0; i < 4; i++) {                                             \
            int id = tid + i * 256; int r = id >> 4, c = (id & 15) * 4;           \
            cp16(su(&Ks[buf][r * KS_STRIDE + c]),                                 \
                 Kp + (size_t)((kv0) + r) * 64 + c);                              \
        }                                                                         \
        _Pragma("unroll")                                                         \
        for (int i = 0; i < 4; i++) {                                             \
            int id = tid + i * 256; int r = id >> 4, c = (id & 15) * 4;           \
            cp16(su(&Vs[buf][r * VS_STRIDE + c]),                                 \
                 Vp + (size_t)((kv0) + r) * 64 + c);                              \
        }                                                                         \
        cpcommit();                                                               \
    } while (0)

    KV_LOAD(0, 0);
    cpwait1();
    __syncthreads();

    // pre-scale Q in smem by SCL (one-time)
#pragma unroll
    for (int i = 0; i < 8; i++) {
        int id = tid + i * 256; int r = id >> 4, c = (id & 15) * 4;
        float4* p = (float4*)&Qs[r * QS_STRIDE + c];
        float4 v = *p;
        v.x *= SCL; v.y *= SCL; v.z *= SCL; v.w *= SCL;
        *p = v;
    }
    __syncthreads();

    float m0r = -1e30f, m1r = -1e30f, l0 = 0.f, l1 = 0.f;
    float o[8][4] = {};

    for (int j = 0; j < 32; j++) {
        if (j + 1 < 32) { KV_LOAD((j + 1) & 1, (j + 1) * 64); cpwait1(); }
        else cpwait0();
        __syncthreads();
        const float* ks = Ks[j & 1];
        const float* vs = Vs[j & 1];

        float acc[8][4];
#pragma unroll
        for (int nb = 0; nb < 8; nb++)
#pragma unroll
            for (int i = 0; i < 4; i++) acc[nb][i] = 0.f;

#pragma unroll
        for (int kb = 0; kb < 8; kb++) {
            unsigned a[4];
            a[0] = __float_as_uint(Qs[(wq0 + g) * QS_STRIDE + kb * 8 + t]);
            a[1] = __float_as_uint(Qs[(wq0 + g + 8) * QS_STRIDE + kb * 8 + t]);
            a[2] = __float_as_uint(Qs[(wq0 + g) * QS_STRIDE + kb * 8 + t + 4]);
            a[3] = __float_as_uint(Qs[(wq0 + g + 8) * QS_STRIDE + kb * 8 + t + 4]);
#pragma unroll
            for (int nb = 0; nb < 8; nb++) {
                unsigned b[2];
                b[0] = __float_as_uint(ks[(nb * 8 + g) * KS_STRIDE + kb * 8 + t]);
                b[1] = __float_as_uint(ks[(nb * 8 + g) * KS_STRIDE + kb * 8 + t + 4]);
                mma8(acc[nb], a, b);
            }
        }

        float mx0 = -1e30f, mx1 = -1e30f;
#pragma unroll
        for (int nb = 0; nb < 8; nb++) {
            mx0 = fmaxf(mx0, fmaxf(acc[nb][0], acc[nb][1]));
            mx1 = fmaxf(mx1, fmaxf(acc[nb][2], acc[nb][3]));
        }
        mx0 = fmaxf(mx0, __shfl_xor_sync(FULL, mx0, 1));
        mx0 = fmaxf(mx0, __shfl_xor_sync(FULL, mx0, 2));
        mx1 = fmaxf(mx1, __shfl_xor_sync(FULL, mx1, 1));
        mx1 = fmaxf(mx1, __shfl_xor_sync(FULL, mx1, 2));

        float mn0 = fmaxf(m0r, mx0), mn1 = fmaxf(m1r, mx1);
        float al0 = ex2(m0r - mn0), al1 = ex2(m1r - mn1);
        m0r = mn0; m1r = mn1;

        float s0 = 0.f, s1 = 0.f;
#pragma unroll
        for (int nb = 0; nb < 8; nb++) {
            float p0 = ex2(acc[nb][0] - mn0);
            float p1 = ex2(acc[nb][1] - mn0);
            float p2 = ex2(acc[nb][2] - mn1);
            float p3 = ex2(acc[nb][3] - mn1);
            s0 += p0 + p1; s1 += p2 + p3;
            acc[nb][0] = p0; acc[nb][1] = p1;
            acc[nb][2] = p2; acc[nb][3] = p3;
        }
        s0 += __shfl_xor_sync(FULL, s0, 1);
        s0 += __shfl_xor_sync(FULL, s0, 2);
        s1 += __shfl_xor_sync(FULL, s1, 1);
        s1 += __shfl_xor_sync(FULL, s1, 2);
        l0 = l0 * al0 + s0;
        l1 = l1 * al1 + s1;

#pragma unroll
        for (int nb = 0; nb < 8; nb++) {
            o[nb][0] *= al0; o[nb][1] *= al0;
            o[nb][2] *= al1; o[nb][3] *= al1;
        }

        const int srcA = (lane & ~3) | (t >> 1);
        const int srcB = srcA + 2;
        const bool odd = (t & 1);
#pragma unroll
        for (int kb = 0; kb < 8; kb++) {
            float v0 = __shfl_sync(FULL, acc[kb][0], srcA);
            float v1 = __shfl_sync(FULL, acc[kb][1], srcA);
            float w0 = __shfl_sync(FULL, acc[kb][2], srcA);
            float w1 = __shfl_sync(FULL, acc[kb][3], srcA);
            float x0 = __shfl_sync(FULL, acc[kb][0], srcB);
            float x1 = __shfl_sync(FULL, acc[kb][1], srcB);
            float y0 = __shfl_sync(FULL, acc[kb][2], srcB);
            float y1 = __shfl_sync(FULL, acc[kb][3], srcB);
            unsigned ap[4];
            ap[0] = __float_as_uint(odd ? v1 : v0);
            ap[1] = __float_as_uint(odd ? w1 : w0);
            ap[2] = __float_as_uint(odd ? x1 : x0);
            ap[3] = __float_as_uint(odd ? y1 : y0);
#pragma unroll
            for (int nb = 0; nb < 8; nb++) {
                unsigned b[2];
                b[0] = __float_as_uint(vs[(kb * 8 + t) * VS_STRIDE + nb * 8 + g]);
                b[1] = __float_as_uint(vs[(kb * 8 + t + 4) * VS_STRIDE + nb * 8 + g]);
                mma8(o[nb], ap, b);
            }
        }
        __syncthreads();
    }

    float inv0 = 1.f / l0, inv1 = 1.f / l1;
#pragma unroll
    for (int nb = 0; nb < 8; nb++) {
        int c0 = nb * 8 + t * 2;
        {
            int r = m0 + wq0 + g;
            float2 v;
            v.x = o[nb][0] * inv0;
            v.y = o[nb][1] * inv0;
            *(float2*)&Op[(size_t)r * 64 + c0] = v;
        }
        {
            int r = m0 + wq0 + g + 8;
            float2 v;
            v.x = o[nb][2] * inv1;
            v.y = o[nb][3] * inv1;
            *(float2*)&Op[(size_t)r * 64 + c0] = v;
        }
    }
}

// ============================================================
// Kernel 3: out = untranspose(Og) @ wo + bo, tf32 mma
// ============================================================
__global__ __launch_bounds__(256, 2) void outproj_tc_kernel(
    const float* __restrict__ W, const float* __restrict__ bo,
    float* __restrict__ out)
{
    extern __shared__ float sm[];
    float* Asm[2] = { sm, sm + 4608 };
    float* Bsm[2] = { sm + 9216, sm + 9216 + 4352 };

    const int tid = threadIdx.x;
    const int m0 = blockIdx.y * 128, n0 = blockIdx.x * 128;
    const int warp = tid >> 5, lane = tid & 31;
    const int g = lane >> 2, t = lane & 3;
    const int wm = (warp & 3) * 32, wn = (warp >> 2) * 64;

    float acc[2][8][4] = {};

#define OP_LOAD(buf, k0)                                                          \
    do {                                                                          \
        _Pragma("unroll")                                                         \
        for (int i = 0; i < 4; i++) {                                             \
            int id = tid + i * 256; int r = id >> 3, cc = id & 7;                 \
            int m = m0 + r; int k = (k0) + cc * 4;                                \
            const float* src = Og + (((size_t)((m >> 11) * 16 + (k >> 6))) * 2048 \
                                     + (m & 2047)) * 64 + (k & 63);               \
            cp16(su(&Asm[buf][r * 36 + cc * 4]), src);                            \
        }                                                                         \
        _Pragma("unroll")                                                         \
        for (int i = 0; i < 4; i++) {                                             \
            int id = tid + i * 256; int r = id >> 5, cc = id & 31;                \
            cp16(su(&Bsm[buf][r * 136 + cc * 4]),                                 \
                 W + (size_t)((k0) + r) * 1024 + n0 + cc * 4);                    \
        }                                                                         \
        cpcommit();                                                               \
    } while (0)

    OP_LOAD(0, 0);
    for (int it = 0; it < 32; it++) {
        if (it + 1 < 32) { OP_LOAD((it + 1) & 1, (it + 1) * 32); cpwait1(); }
        else cpwait0();
        __syncthreads();
        const float* a_s = Asm[it & 1];
        const float* b_s = Bsm[it & 1];
#pragma unroll
        for (int ks = 0; ks < 32; ks += 8) {
            unsigned a[2][4], b[8][2];
#pragma unroll
            for (int ma = 0; ma < 2; ma++) {
                int rb = wm + ma * 16;
                a[ma][0] = __float_as_uint(a_s[(rb + g) * 36 + ks + t]);
                a[ma][1] = __float_as_uint(a_s[(rb + g + 8) * 36 + ks + t]);
                a[ma][2] = __float_as_uint(a_s[(rb + g) * 36 + ks + t + 4]);
                a[ma][3] = __float_as_uint(a_s[(rb + g + 8) * 36 + ks + t + 4]);
            }
#pragma unroll
            for (int nb = 0; nb < 8; nb++) {
                b[nb][0] = __float_as_uint(b_s[(ks + t) * 136 + wn + nb * 8 + g]);
                b[nb][1] = __float_as_uint(b_s[(ks + t + 4) * 136 + wn + nb * 8 + g]);
            }
#pragma unroll
            for (int nb = 0; nb < 8; nb++)
#pragma unroll
                for (int ma = 0; ma < 2; ma++)
                    mma8(acc[ma][nb], a[ma], b[nb]);
        }
        __syncthreads();
    }

#pragma unroll
    for (int ma = 0; ma < 2; ma++)
#pragma unroll
        for (int nb = 0; nb < 8; nb++) {
            int c0 = n0 + wn + nb * 8 + t * 2;
            float b0 = __ldg(&bo[c0]), b1 = __ldg(&bo[c0 + 1]);
#pragma unroll
            for (int rr = 0; rr < 2; rr++) {
                int r = m0 + wm + ma * 16 + g + rr * 8;
                float2 v;
                v.x = acc[ma][nb][rr * 2 + 0] + b0;
                v.y = acc[ma][nb][rr * 2 + 1] + b1;
                *(float2*)&out[(size_t)r * 1024 + c0] = v;
            }
        }
}

// ============================================================
extern "C" void kernel_launch(void* const* d_in, const int* in_sizes, int n_in,
                              void* d_out, int out_size)
{
    const float* x  = (const float*)d_in[0];
    const float* wq = (const float*)d_in[1];
    const float* bq = (const float*)d_in[2];
    const float* wk = (const float*)d_in[3];
    const float* bk = (const float*)d_in[4];
    const float* wv = (const float*)d_in[5];
    const float* bv = (const float*)d_in[6];
    const float* wo = (const float*)d_in[7];
    const float* bo = (const float*)d_in[8];
    float* out = (float*)d_out;

    cudaFuncSetAttribute(proj_qkv_kernel,   cudaFuncAttributeMaxDynamicSharedMemorySize, 71680);
    cudaFuncSetAttribute(flash_attn_kernel, cudaFuncAttributeMaxDynamicSharedMemorySize, 106496);
    cudaFuncSetAttribute(outproj_tc_kernel, cudaFuncAttributeMaxDynamicSharedMemorySize, 71680);

    float* Xr_p; cudaGetSymbolAddress((void**)&Xr_p, Xr);
    float* Wr_p; cudaGetSymbolAddress((void**)&Wr_p, Wr);
    float* Qp;   cudaGetSymbolAddress((void**)&Qp, Qg);
    float* Kp;   cudaGetSymbolAddress((void**)&Kp, Kg);
    float* Vp;   cudaGetSymbolAddress((void**)&Vp, Vg);

    // fill device-side out-pointer table (graph-capturable async memcpy)
    static float* h_tab[3];
    h_tab[0] = Qp; h_tab[1] = Kp; h_tab[2] = Vp;
    void* tab_dev; cudaGetSymbolAddress(&tab_dev, QKVout);
    cudaMemcpyAsync(tab_dev, h_tab, sizeof(h_tab), cudaMemcpyHostToDevice);

    dim3 blk(256);
    const size_t WSZ = (size_t)D_MODEL * D_MODEL;

    {
        int n4 = (MROWS * D_MODEL) / 4;
        round_x_kernel<<<(n4 + 255) / 256, blk>>>(x, Xr_p, n4);
        int w4 = (int)(WSZ / 4);
        round_w_kernel<<<dim3((w4 + 255) / 256, 4), blk>>>(wq, wk, wv, wo, Wr_p, w4);
    }

    // merged QKV: one launch, grid.z selects projection (1536 CTAs total)
    dim3 gqkv(D_MODEL / 128, MROWS / 128, 3);
    proj_qkv_kernel<<<gqkv, blk, 71680>>>(Xr_p, Wr_p, bq, bk, bv);

    flash_attn_kernel<<<dim3(SEQ / 128, BH), blk, 106496>>>();

    outproj_tc_kernel<<<dim3(D_MODEL / 128, MROWS / 128), blk, 71680>>>(
        Wr_p + 3 * WSZ, bo, out);
}

// round 9
// speedup vs baseline: 1.1690x; 1.1018x over previous
#include <cuda_runtime.h>
#include <cuda_bf16.h>

#define D_MODEL 1024
#define HEADS   16
#define DEPTH   64
#define BATCH   4
#define SEQ     2048
#define MROWS   (BATCH * SEQ)   /* 8192 */
#define BH      (BATCH * HEADS) /* 64   */

// ---- static scratch (allocation-free per harness rules) ----
__device__ float Qg[(size_t)BH * SEQ * DEPTH];   // [bh][s][d]
__device__ float Kg[(size_t)BH * SEQ * DEPTH];
__device__ float Vg[(size_t)BH * SEQ * DEPTH];
__device__ float Og[(size_t)BH * SEQ * DEPTH];   // attention out
__device__ float Xr[(size_t)MROWS * D_MODEL];    // x rounded to tf32
__device__ float Wr[(size_t)4 * D_MODEL * D_MODEL]; // wq,wk,wv,wo rounded

// device-side output pointer table for merged QKV kernel
__device__ float* QKVout[3];

// ---------------- helpers ----------------
__device__ __forceinline__ unsigned su(const void* p) {
    return (unsigned)__cvta_generic_to_shared(p);
}
__device__ __forceinline__ void cp16(unsigned d, const void* s) {
    asm volatile("cp.async.cg.shared.global [%0], [%1], 16;" :: "r"(d), "l"(s));
}
__device__ __forceinline__ void cpcommit() { asm volatile("cp.async.commit_group;"); }
__device__ __forceinline__ void cpwait0() { asm volatile("cp.async.wait_group 0;"); }
__device__ __forceinline__ void cpwait1() { asm volatile("cp.async.wait_group 1;"); }

__device__ __forceinline__ float tf32r(float x) {
    unsigned u;
    asm("cvt.rna.tf32.f32 %0, %1;" : "=r"(u) : "f"(x));
    return __uint_as_float(u);
}
__device__ __forceinline__ float ex2(float x) {
    float r;
    asm("ex2.approx.f32 %0, %1;" : "=f"(r) : "f"(x));
    return r;
}
__device__ __forceinline__ void mma8(float* c, const unsigned* a, const unsigned* b) {
    asm volatile(
        "mma.sync.aligned.m16n8k8.row.col.f32.tf32.tf32.f32 "
        "{%0,%1,%2,%3},{%4,%5,%6,%7},{%8,%9},{%0,%1,%2,%3};"
        : "+f"(c[0]), "+f"(c[1]), "+f"(c[2]), "+f"(c[3])
        : "r"(a[0]), "r"(a[1]), "r"(a[2]), "r"(a[3]), "r"(b[0]), "r"(b[1]));
}

// ---------------- kernel 0a: round x -> tf32 ----------------
__global__ __launch_bounds__(256) void round_x_kernel(
    const float* __restrict__ in, float* __restrict__ out, int n4)
{
    int i = blockIdx.x * 256 + threadIdx.x;
    if (i < n4) {
        float4 v = ((const float4*)in)[i];
        v.x = tf32r(v.x); v.y = tf32r(v.y); v.z = tf32r(v.z); v.w = tf32r(v.w);
        ((float4*)out)[i] = v;
    }
}

// ---------------- kernel 0b: round all 4 weights (one launch) ----------------
__global__ __launch_bounds__(256) void round_w_kernel(
    const float* __restrict__ w0, const float* __restrict__ w1,
    const float* __restrict__ w2, const float* __restrict__ w3,
    float* __restrict__ out, int n4)
{
    const float* src = (blockIdx.y == 0) ? w0 : (blockIdx.y == 1) ? w1
                       : (blockIdx.y == 2) ? w2 : w3;
    float* dst = out + (size_t)blockIdx.y * (size_t)D_MODEL * D_MODEL;
    int i = blockIdx.x * 256 + threadIdx.x;
    if (i < n4) {
        float4 v = ((const float4*)src)[i];
        v.x = tf32r(v.x); v.y = tf32r(v.y); v.z = tf32r(v.z); v.w = tf32r(v.w);
        ((float4*)dst)[i] = v;
    }
}

// ============================================================
// Kernel 1: MERGED QKV proj — grid.z selects {Q,K,V}
// ============================================================
__global__ __launch_bounds__(256, 2) void proj_qkv_kernel(
    const float* __restrict__ A, const float* __restrict__ Wbase,
    const float* __restrict__ bq, const float* __restrict__ bk,
    const float* __restrict__ bv)
{
    extern __shared__ float sm[];
    float* Asm[2] = { sm, sm + 4608 };               // 128 rows x stride 36
    float* Bsm[2] = { sm + 9216, sm + 9216 + 4352 }; // 32 rows x stride 136

    const int z = blockIdx.z;
    const float* W = Wbase + (size_t)z * D_MODEL * D_MODEL;
    const float* bias = (z == 0) ? bq : (z == 1) ? bk : bv;
    float* out = QKVout[z];

    const int tid = threadIdx.x;
    const int m0 = blockIdx.y * 128, n0 = blockIdx.x * 128;
    const int warp = tid >> 5, lane = tid & 31;
    const int g = lane >> 2, t = lane & 3;
    const int wm = (warp & 3) * 32, wn = (warp >> 2) * 64;

    float acc[2][8][4] = {};

#define PROJ_LOAD(buf, k0)                                                        \
    do {                                                                          \
        _Pragma("unroll")                                                         \
        for (int i = 0; i < 4; i++) {                                             \
            int id = tid + i * 256; int r = id >> 3, cc = id & 7;                 \
            cp16(su(&Asm[buf][r * 36 + cc * 4]),                                  \
                 A + (size_t)(m0 + r) * 1024 + (k0) + cc * 4);                    \
        }                                                                         \
        _Pragma("unroll")                                                         \
        for (int i = 0; i < 4; i++) {                                             \
            int id = tid + i * 256; int r = id >> 5, cc = id & 31;                \
            cp16(su(&Bsm[buf][r * 136 + cc * 4]),                                 \
                 W + (size_t)((k0) + r) * 1024 + n0 + cc * 4);                    \
        }                                                                         \
        cpcommit();                                                               \
    } while (0)

    PROJ_LOAD(0, 0);
    for (int it = 0; it < 32; it++) {
        if (it + 1 < 32) { PROJ_LOAD((it + 1) & 1, (it + 1) * 32); cpwait1(); }
        else cpwait0();
        __syncthreads();
        const float* a_s = Asm[it & 1];
        const float* b_s = Bsm[it & 1];
#pragma unroll
        for (int ks = 0; ks < 32; ks += 8) {
            unsigned a[2][4], b[8][2];
#pragma unroll
            for (int ma = 0; ma < 2; ma++) {
                int rb = wm + ma * 16;
                a[ma][0] = __float_as_uint(a_s[(rb + g) * 36 + ks + t]);
                a[ma][1] = __float_as_uint(a_s[(rb + g + 8) * 36 + ks + t]);
                a[ma][2] = __float_as_uint(a_s[(rb + g) * 36 + ks + t + 4]);
                a[ma][3] = __float_as_uint(a_s[(rb + g + 8) * 36 + ks + t + 4]);
            }
#pragma unroll
            for (int nb = 0; nb < 8; nb++) {
                b[nb][0] = __float_as_uint(b_s[(ks + t) * 136 + wn + nb * 8 + g]);
                b[nb][1] = __float_as_uint(b_s[(ks + t + 4) * 136 + wn + nb * 8 + g]);
            }
#pragma unroll
            for (int nb = 0; nb < 8; nb++)
#pragma unroll
                for (int ma = 0; ma < 2; ma++)
                    mma8(acc[ma][nb], a[ma], b[nb]);
        }
        __syncthreads();
    }

#pragma unroll
    for (int ma = 0; ma < 2; ma++)
#pragma unroll
        for (int nb = 0; nb < 8; nb++) {
            int c0 = n0 + wn + nb * 8 + t * 2;
            float b0 = __ldg(&bias[c0]), b1 = __ldg(&bias[c0 + 1]);
            int h = c0 >> 6, d = c0 & 63;
#pragma unroll
            for (int rr = 0; rr < 2; rr++) {
                int r = m0 + wm + ma * 16 + g + rr * 8;
                int bb = r >> 11, ss = r & 2047;
                float2 v;
                v.x = acc[ma][nb][rr * 2 + 0] + b0;
                v.y = acc[ma][nb][rr * 2 + 1] + b1;
                *(float2*)&out[(((size_t)(bb * 16 + h)) * 2048 + ss) * 64 + d] = v;
            }
        }
}

// ============================================================
// Kernel 2: FLASH ATTENTION — 4 warps x 32 Q-rows, 64-row KV
//   128 threads/CTA, 2 CTAs/SM. B-fragments shared by 2 m-tiles.
// ============================================================
#define QS_STRIDE 68
#define KS_STRIDE 68
#define VS_STRIDE 72
#define SCL (0.125f * 1.4426950408889634f)   /* 1/sqrt(64) * log2(e) */

__global__ __launch_bounds__(128, 2) void flash_attn_kernel()
{
    extern __shared__ float sm[];
    float* Qs = sm;                                   // 128 x 68 = 8704
    float* Ks[2] = { sm + 8704,  sm + 13056 };        // each 64 x 68 = 4352
    float* Vs[2] = { sm + 17408, sm + 22016 };        // each 64 x 72 = 4608

    const int bh = blockIdx.y;
    const int m0 = blockIdx.x * 128;
    const float* Qp = Qg + (size_t)bh * SEQ * DEPTH;
    const float* Kp = Kg + (size_t)bh * SEQ * DEPTH;
    const float* Vp = Vg + (size_t)bh * SEQ * DEPTH;
    float* Op = Og + (size_t)bh * SEQ * DEPTH;

    const int tid = threadIdx.x;
    const int warp = tid >> 5, lane = tid & 31;
    const int g = lane >> 2, t = lane & 3;
    const int wq0 = warp * 32;                  // warp owns 32 Q rows
    const unsigned FULL = 0xffffffffu;

    // ---- load Q tile (128x64): 16 float4 per thread ----
#pragma unroll
    for (int i = 0; i < 16; i++) {
        int id = tid + i * 128; int r = id >> 4, c = (id & 15) * 4;
        cp16(su(&Qs[r * QS_STRIDE + c]), Qp + (size_t)(m0 + r) * 64 + c);
    }
    cpcommit();

    // ---- 64-row KV tiles: 8 float4 per thread each ----
#define KV_LOAD(buf, kv0)                                                         \
    do {                                                                          \
        _Pragma("unroll")                                                         \
        for (int i = 0; i < 8; i++) {                                             \
            int id = tid + i * 128; int r = id >> 4, c = (id & 15) * 4;           \
            cp16(su(&Ks[buf][r * KS_STRIDE + c]),                                 \
                 Kp + (size_t)((kv0) + r) * 64 + c);                              \
        }                                                                         \
        _Pragma("unroll")                                                         \
        for (int i = 0; i < 8; i++) {                                             \
            int id = tid + i * 128; int r = id >> 4, c = (id & 15) * 4;           \
            cp16(su(&Vs[buf][r * VS_STRIDE + c]),                                 \
                 Vp + (size_t)((kv0) + r) * 64 + c);                              \
        }                                                                         \
        cpcommit();                                                               \
    } while (0)

    KV_LOAD(0, 0);
    cpwait1();
    __syncthreads();

    // ---- pre-scale Q in smem by SCL (one-time) ----
#pragma unroll
    for (int i = 0; i < 16; i++) {
        int id = tid + i * 128; int r = id >> 4, c = (id & 15) * 4;
        float4* p = (float4*)&Qs[r * QS_STRIDE + c];
        float4 v = *p;
        v.x *= SCL; v.y *= SCL; v.z *= SCL; v.w *= SCL;
        *p = v;
    }
    __syncthreads();

    // softmax state: 4 row-states (ma in {0,1} x {rows g, rows g+8})
    float mr[4] = { -1e30f, -1e30f, -1e30f, -1e30f };
    float lr[4] = { 0.f, 0.f, 0.f, 0.f };
    float o[2][8][4] = {};

    for (int j = 0; j < 32; j++) {
        if (j + 1 < 32) { KV_LOAD((j + 1) & 1, (j + 1) * 64); cpwait1(); }
        else cpwait0();
        __syncthreads();
        const float* ks = Ks[j & 1];
        const float* vs = Vs[j & 1];

        // ---- S = (Q*scl) K^T : warp tile 32 x 64 (2 m-tiles) ----
        float acc[2][8][4];
#pragma unroll
        for (int ma = 0; ma < 2; ma++)
#pragma unroll
            for (int nb = 0; nb < 8; nb++)
#pragma unroll
                for (int i = 0; i < 4; i++) acc[ma][nb][i] = 0.f;

#pragma unroll
        for (int kb = 0; kb < 8; kb++) {
            unsigned a[2][4];
#pragma unroll
            for (int ma = 0; ma < 2; ma++) {
                int rb = wq0 + ma * 16;
                a[ma][0] = __float_as_uint(Qs[(rb + g) * QS_STRIDE + kb * 8 + t]);
                a[ma][1] = __float_as_uint(Qs[(rb + g + 8) * QS_STRIDE + kb * 8 + t]);
                a[ma][2] = __float_as_uint(Qs[(rb + g) * QS_STRIDE + kb * 8 + t + 4]);
                a[ma][3] = __float_as_uint(Qs[(rb + g + 8) * QS_STRIDE + kb * 8 + t + 4]);
            }
#pragma unroll
            for (int nb = 0; nb < 8; nb++) {
                unsigned b[2];
                b[0] = __float_as_uint(ks[(nb * 8 + g) * KS_STRIDE + kb * 8 + t]);
                b[1] = __float_as_uint(ks[(nb * 8 + g) * KS_STRIDE + kb * 8 + t + 4]);
                mma8(acc[0][nb], a[0], b);
                mma8(acc[1][nb], a[1], b);
            }
        }

        // ---- online softmax, log2 domain, 4 row-states ----
        float mx[4] = { -1e30f, -1e30f, -1e30f, -1e30f };
#pragma unroll
        for (int ma = 0; ma < 2; ma++)
#pragma unroll
            for (int nb = 0; nb < 8; nb++) {
                mx[ma * 2 + 0] = fmaxf(mx[ma * 2 + 0], fmaxf(acc[ma][nb][0], acc[ma][nb][1]));
                mx[ma * 2 + 1] = fmaxf(mx[ma * 2 + 1], fmaxf(acc[ma][nb][2], acc[ma][nb][3]));
            }
        float al[4];
#pragma unroll
        for (int s = 0; s < 4; s++) {
            mx[s] = fmaxf(mx[s], __shfl_xor_sync(FULL, mx[s], 1));
            mx[s] = fmaxf(mx[s], __shfl_xor_sync(FULL, mx[s], 2));
            float mn = fmaxf(mr[s], mx[s]);
            al[s] = ex2(mr[s] - mn);
            mr[s] = mn;
        }

        float sum[4] = { 0.f, 0.f, 0.f, 0.f };
#pragma unroll
        for (int ma = 0; ma < 2; ma++)
#pragma unroll
            for (int nb = 0; nb < 8; nb++) {
                float p0 = ex2(acc[ma][nb][0] - mr[ma * 2 + 0]);
                float p1 = ex2(acc[ma][nb][1] - mr[ma * 2 + 0]);
                float p2 = ex2(acc[ma][nb][2] - mr[ma * 2 + 1]);
                float p3 = ex2(acc[ma][nb][3] - mr[ma * 2 + 1]);
                sum[ma * 2 + 0] += p0 + p1;
                sum[ma * 2 + 1] += p2 + p3;
                acc[ma][nb][0] = p0; acc[ma][nb][1] = p1;
                acc[ma][nb][2] = p2; acc[ma][nb][3] = p3;
            }
#pragma unroll
        for (int s = 0; s < 4; s++) {
            sum[s] += __shfl_xor_sync(FULL, sum[s], 1);
            sum[s] += __shfl_xor_sync(FULL, sum[s], 2);
            lr[s] = lr[s] * al[s] + sum[s];
        }

        // rescale O
#pragma unroll
        for (int ma = 0; ma < 2; ma++)
#pragma unroll
            for (int nb = 0; nb < 8; nb++) {
                o[ma][nb][0] *= al[ma * 2 + 0]; o[ma][nb][1] *= al[ma * 2 + 0];
                o[ma][nb][2] *= al[ma * 2 + 1]; o[ma][nb][3] *= al[ma * 2 + 1];
            }

        // ---- O += P @ V : C-frag -> A-frag via shuffles; b shared by m-tiles ----
        const int srcA = (lane & ~3) | (t >> 1);
        const int srcB = srcA + 2;
        const bool odd = (t & 1);
#pragma unroll
        for (int kb = 0; kb < 8; kb++) {
            unsigned ap[2][4];
#pragma unroll
            for (int ma = 0; ma < 2; ma++) {
                float v0 = __shfl_sync(FULL, acc[ma][kb][0], srcA);
                float v1 = __shfl_sync(FULL, acc[ma][kb][1], srcA);
                float w0 = __shfl_sync(FULL, acc[ma][kb][2], srcA);
                float w1 = __shfl_sync(FULL, acc[ma][kb][3], srcA);
                float x0 = __shfl_sync(FULL, acc[ma][kb][0], srcB);
                float x1 = __shfl_sync(FULL, acc[ma][kb][1], srcB);
                float y0 = __shfl_sync(FULL, acc[ma][kb][2], srcB);
                float y1 = __shfl_sync(FULL, acc[ma][kb][3], srcB);
                ap[ma][0] = __float_as_uint(odd ? v1 : v0);
                ap[ma][1] = __float_as_uint(odd ? w1 : w0);
                ap[ma][2] = __float_as_uint(odd ? x1 : x0);
                ap[ma][3] = __float_as_uint(odd ? y1 : y0);
            }
#pragma unroll
            for (int nb = 0; nb < 8; nb++) {
                unsigned b[2];
                b[0] = __float_as_uint(vs[(kb * 8 + t) * VS_STRIDE + nb * 8 + g]);
                b[1] = __float_as_uint(vs[(kb * 8 + t + 4) * VS_STRIDE + nb * 8 + g]);
                mma8(o[0][nb], ap[0], b);
                mma8(o[1][nb], ap[1], b);
            }
        }
        __syncthreads();
    }

    // ---- epilogue: O /= l, store ----
    float inv[4];
#pragma unroll
    for (int s = 0; s < 4; s++) inv[s] = 1.f / lr[s];
#pragma unroll
    for (int ma = 0; ma < 2; ma++)
#pragma unroll
        for (int nb = 0; nb < 8; nb++) {
            int c0 = nb * 8 + t * 2;
            {
                int r = m0 + wq0 + ma * 16 + g;
                float2 v;
                v.x = o[ma][nb][0] * inv[ma * 2 + 0];
                v.y = o[ma][nb][1] * inv[ma * 2 + 0];
                *(float2*)&Op[(size_t)r * 64 + c0] = v;
            }
            {
                int r = m0 + wq0 + ma * 16 + g + 8;
                float2 v;
                v.x = o[ma][nb][2] * inv[ma * 2 + 1];
                v.y = o[ma][nb][3] * inv[ma * 2 + 1];
                *(float2*)&Op[(size_t)r * 64 + c0] = v;
            }
        }
}

// ============================================================
// Kernel 3: out = untranspose(Og) @ wo + bo, tf32 mma
// ============================================================
__global__ __launch_bounds__(256, 2) void outproj_tc_kernel(
    const float* __restrict__ W, const float* __restrict__ bo,
    float* __restrict__ out)
{
    extern __shared__ float sm[];
    float* Asm[2] = { sm, sm + 4608 };
    float* Bsm[2] = { sm + 9216, sm + 9216 + 4352 };

    const int tid = threadIdx.x;
    const int m0 = blockIdx.y * 128, n0 = blockIdx.x * 128;
    const int warp = tid >> 5, lane = tid & 31;
    const int g = lane >> 2, t = lane & 3;
    const int wm = (warp & 3) * 32, wn = (warp >> 2) * 64;

    float acc[2][8][4] = {};

#define OP_LOAD(buf, k0)                                                          \
    do {                                                                          \
        _Pragma("unroll")                                                         \
        for (int i = 0; i < 4; i++) {                                             \
            int id = tid + i * 256; int r = id >> 3, cc = id & 7;                 \
            int m = m0 + r; int k = (k0) + cc * 4;                                \
            const float* src = Og + (((size_t)((m >> 11) * 16 + (k >> 6))) * 2048 \
                                     + (m & 2047)) * 64 + (k & 63);               \
            cp16(su(&Asm[buf][r * 36 + cc * 4]), src);                            \
        }                                                                         \
        _Pragma("unroll")                                                         \
        for (int i = 0; i < 4; i++) {                                             \
            int id = tid + i * 256; int r = id >> 5, cc = id & 31;                \
            cp16(su(&Bsm[buf][r * 136 + cc * 4]),                                 \
                 W + (size_t)((k0) + r) * 1024 + n0 + cc * 4);                    \
        }                                                                         \
        cpcommit();                                                               \
    } while (0)

    OP_LOAD(0, 0);
    for (int it = 0; it < 32; it++) {
        if (it + 1 < 32) { OP_LOAD((it + 1) & 1, (it + 1) * 32); cpwait1(); }
        else cpwait0();
        __syncthreads();
        const float* a_s = Asm[it & 1];
        const float* b_s = Bsm[it & 1];
#pragma unroll
        for (int ks = 0; ks < 32; ks += 8) {
            unsigned a[2][4], b[8][2];
#pragma unroll
            for (int ma = 0; ma < 2; ma++) {
                int rb = wm + ma * 16;
                a[ma][0] = __float_as_uint(a_s[(rb + g) * 36 + ks + t]);
                a[ma][1] = __float_as_uint(a_s[(rb + g + 8) * 36 + ks + t]);
                a[ma][2] = __float_as_uint(a_s[(rb + g) * 36 + ks + t + 4]);
                a[ma][3] = __float_as_uint(a_s[(rb + g + 8) * 36 + ks + t + 4]);
            }
#pragma unroll
            for (int nb = 0; nb < 8; nb++) {
                b[nb][0] = __float_as_uint(b_s[(ks + t) * 136 + wn + nb * 8 + g]);
                b[nb][1] = __float_as_uint(b_s[(ks + t + 4) * 136 + wn + nb * 8 + g]);
            }
#pragma unroll
            for (int nb = 0; nb < 8; nb++)
#pragma unroll
                for (int ma = 0; ma < 2; ma++)
                    mma8(acc[ma][nb], a[ma], b[nb]);
        }
        __syncthreads();
    }

#pragma unroll
    for (int ma = 0; ma < 2; ma++)
#pragma unroll
        for (int nb = 0; nb < 8; nb++) {
            int c0 = n0 + wn + nb * 8 + t * 2;
            float b0 = __ldg(&bo[c0]), b1 = __ldg(&bo[c0 + 1]);
#pragma unroll
            for (int rr = 0; rr < 2; rr++) {
                int r = m0 + wm + ma * 16 + g + rr * 8;
                float2 v;
                v.x = acc[ma][nb][rr * 2 + 0] + b0;
                v.y = acc[ma][nb][rr * 2 + 1] + b1;
                *(float2*)&out[(size_t)r * 1024 + c0] = v;
            }
        }
}

// ============================================================
extern "C" void kernel_launch(void* const* d_in, const int* in_sizes, int n_in,
                              void* d_out, int out_size)
{
    const float* x  = (const float*)d_in[0];
    const float* wq = (const float*)d_in[1];
    const float* bq = (const float*)d_in[2];
    const float* wk = (const float*)d_in[3];
    const float* bk = (const float*)d_in[4];
    const float* wv = (const float*)d_in[5];
    const float* bv = (const float*)d_in[6];
    const float* wo = (const float*)d_in[7];
    const float* bo = (const float*)d_in[8];
    float* out = (float*)d_out;

    cudaFuncSetAttribute(proj_qkv_kernel,   cudaFuncAttributeMaxDynamicSharedMemorySize, 71680);
    cudaFuncSetAttribute(flash_attn_kernel, cudaFuncAttributeMaxDynamicSharedMemorySize, 106496);
    cudaFuncSetAttribute(outproj_tc_kernel, cudaFuncAttributeMaxDynamicSharedMemorySize, 71680);

    float* Xr_p; cudaGetSymbolAddress((void**)&Xr_p, Xr);
    float* Wr_p; cudaGetSymbolAddress((void**)&Wr_p, Wr);
    float* Qp;   cudaGetSymbolAddress((void**)&Qp, Qg);
    float* Kp;   cudaGetSymbolAddress((void**)&Kp, Kg);
    float* Vp;   cudaGetSymbolAddress((void**)&Vp, Vg);

    // fill device-side out-pointer table (graph-capturable async memcpy)
    static float* h_tab[3];
    h_tab[0] = Qp; h_tab[1] = Kp; h_tab[2] = Vp;
    void* tab_dev; cudaGetSymbolAddress(&tab_dev, QKVout);
    cudaMemcpyAsync(tab_dev, h_tab, sizeof(h_tab), cudaMemcpyHostToDevice);

    dim3 blk(256);
    const size_t WSZ = (size_t)D_MODEL * D_MODEL;

    {
        int n4 = (MROWS * D_MODEL) / 4;
        round_x_kernel<<<(n4 + 255) / 256, blk>>>(x, Xr_p, n4);
        int w4 = (int)(WSZ / 4);
        round_w_kernel<<<dim3((w4 + 255) / 256, 4), blk>>>(wq, wk, wv, wo, Wr_p, w4);
    }

    // merged QKV: one launch, grid.z selects projection
    dim3 gqkv(D_MODEL / 128, MROWS / 128, 3);
    proj_qkv_kernel<<<gqkv, blk, 71680>>>(Xr_p, Wr_p, bq, bk, bv);

    flash_attn_kernel<<<dim3(SEQ / 128, BH), dim3(128), 106496>>>();

    outproj_tc_kernel<<<dim3(D_MODEL / 128, MROWS / 128), blk, 71680>>>(
        Wr_p + 3 * WSZ, bo, out);
}

// round 11
// speedup vs baseline: 2.1626x; 1.8500x over previous
#include <cuda_runtime.h>
#include <cuda_fp16.h>

#define D_MODEL 1024
#define HEADS   16
#define DEPTH   64
#define BATCH   4
#define SEQ     2048
#define MROWS   (BATCH * SEQ)   /* 8192 */
#define BH      (BATCH * HEADS) /* 64   */

// ---- static scratch (allocation-free per harness rules) ----
__device__ __half Xh[(size_t)MROWS * D_MODEL];        // x in fp16
__device__ __half Wth[(size_t)4 * D_MODEL * D_MODEL]; // W^T fp16: [4][n][k]
__device__ __half Qh[(size_t)BH * SEQ * DEPTH];       // [bh][s][d], pre-scaled
__device__ __half Kh[(size_t)BH * SEQ * DEPTH];       // [bh][s][d]
__device__ __half Vh[(size_t)BH * DEPTH * SEQ];       // TRANSPOSED [bh][d][s]
__device__ __half Oh[(size_t)BH * SEQ * DEPTH];       // [bh][s][d]

__device__ __half* QKVout16[3];

#define SCL_F (0.125f * 1.4426950408889634f)   /* 1/sqrt(64) * log2(e) */

// ---------------- helpers ----------------
__device__ __forceinline__ unsigned su(const void* p) {
    return (unsigned)__cvta_generic_to_shared(p);
}
__device__ __forceinline__ void cp16(unsigned d, const void* s) {
    asm volatile("cp.async.cg.shared.global [%0], [%1], 16;" :: "r"(d), "l"(s));
}
__device__ __forceinline__ void cpcommit() { asm volatile("cp.async.commit_group;"); }
__device__ __forceinline__ void cpwait0() { asm volatile("cp.async.wait_group 0;"); }
__device__ __forceinline__ void cpwait1() { asm volatile("cp.async.wait_group 1;"); }

__device__ __forceinline__ float ex2(float x) {
    float r;
    asm("ex2.approx.f32 %0, %1;" : "=f"(r) : "f"(x));
    return r;
}
// pack two floats -> half2 (x = low element, y = high element)
__device__ __forceinline__ unsigned h2pack(float x, float y) {
    unsigned r;
    asm("cvt.rn.f16x2.f32 %0, %1, %2;" : "=r"(r) : "f"(y), "f"(x));
    return r;
}
// fp16 mma m16n8k16, fp32 accumulate
__device__ __forceinline__ void mma16(float* c, const unsigned* a, const unsigned* b) {
    asm volatile(
        "mma.sync.aligned.m16n8k16.row.col.f32.f16.f16.f32 "
        "{%0,%1,%2,%3},{%4,%5,%6,%7},{%8,%9},{%0,%1,%2,%3};"
        : "+f"(c[0]), "+f"(c[1]), "+f"(c[2]), "+f"(c[3])
        : "r"(a[0]), "r"(a[1]), "r"(a[2]), "r"(a[3]), "r"(b[0]), "r"(b[1]));
}

#define ST 72   /* smem row stride in halves = 144 bytes; (4g+t)%32 conflict-free */

// ---------------- prep: x -> fp16 ----------------
__global__ __launch_bounds__(256) void cvt_x_kernel(
    const float* __restrict__ in, __half* __restrict__ out, int n4)
{
    int i = blockIdx.x * 256 + threadIdx.x;
    if (i < n4) {
        float4 v = ((const float4*)in)[i];
        uint2 o;
        o.x = h2pack(v.x, v.y);
        o.y = h2pack(v.z, v.w);
        ((uint2*)out)[i] = o;
    }
}

// ---------------- prep: transpose weights -> fp16  Wth[z][n][k] ----------------
__global__ __launch_bounds__(256) void cvt_wT_kernel(
    const float* __restrict__ w0, const float* __restrict__ w1,
    const float* __restrict__ w2, const float* __restrict__ w3,
    __half* __restrict__ out)
{
    __shared__ float t[32][33];
    const float* src = (blockIdx.z == 0) ? w0 : (blockIdx.z == 1) ? w1
                       : (blockIdx.z == 2) ? w2 : w3;
    __half* dst = out + (size_t)blockIdx.z * (size_t)D_MODEL * D_MODEL;
    int bx = blockIdx.x * 32;   // k tile
    int by = blockIdx.y * 32;   // n tile
#pragma unroll
    for (int j = 0; j < 4; j++)
        t[threadIdx.y + j * 8][threadIdx.x] =
            src[(size_t)(bx + threadIdx.y + j * 8) * D_MODEL + by + threadIdx.x];
    __syncthreads();
#pragma unroll
    for (int j = 0; j < 4; j++)
        dst[(size_t)(by + threadIdx.y + j * 8) * D_MODEL + bx + threadIdx.x] =
            __float2half_rn(t[threadIdx.x][threadIdx.y + j * 8]);
}

// ============================================================
// Kernel 1: MERGED QKV proj, fp16 m16n8k16
//   CTA 128x128, K chunks of 64, double-buffered cp.async.
//   z==0: scale by SCL and store Qh;  z==1: Kh;  z==2: Vh TRANSPOSED.
// ============================================================
#define GEMM_SMEM (4 * 128 * ST * 2)   /* 73728 bytes */

__global__ __launch_bounds__(256, 2) void proj_qkv_kernel(
    const __half* __restrict__ A, const __half* __restrict__ Wbase,
    const float* __restrict__ bq, const float* __restrict__ bk,
    const float* __restrict__ bv)
{
    extern __shared__ __half smh[];
    __half* Ah[2] = { smh, smh + 128 * ST };
    __half* Bh[2] = { smh + 2 * 128 * ST, smh + 3 * 128 * ST };

    const int z = blockIdx.z;
    const __half* W = Wbase + (size_t)z * D_MODEL * D_MODEL;
    const float* bias = (z == 0) ? bq : (z == 1) ? bk : bv;
    __half* out = QKVout16[z];

    const int tid = threadIdx.x;
    const int m0 = blockIdx.y * 128, n0 = blockIdx.x * 128;
    const int warp = tid >> 5, lane = tid & 31;
    const int g = lane >> 2, t = lane & 3;
    const int wm = (warp & 3) * 32, wn = (warp >> 2) * 64;

    float acc[2][8][4] = {};

#define PROJ_LOAD(buf, k0)                                                        \
    do {                                                                          \
        _Pragma("unroll")                                                         \
        for (int i = 0; i < 4; i++) {                                             \
            int id = tid + i * 256; int r = id >> 3, cc = id & 7;                 \
            cp16(su(&Ah[buf][r * ST + cc * 8]),                                   \
                 A + (size_t)(m0 + r) * 1024 + (k0) + cc * 8);                    \
        }                                                                         \
        _Pragma("unroll")                                                         \
        for (int i = 0; i < 4; i++) {                                             \
            int id = tid + i * 256; int r = id >> 3, cc = id & 7;                 \
            cp16(su(&Bh[buf][r * ST + cc * 8]),                                   \
                 W + (size_t)(n0 + r) * 1024 + (k0) + cc * 8);                    \
        }                                                                         \
        cpcommit();                                                               \
    } while (0)

    PROJ_LOAD(0, 0);
    for (int it = 0; it < 16; it++) {
        if (it + 1 < 16) { PROJ_LOAD((it + 1) & 1, (it + 1) * 64); cpwait1(); }
        else cpwait0();
        __syncthreads();
        const __half* a_s = Ah[it & 1];
        const __half* b_s = Bh[it & 1];
#pragma unroll
        for (int ks = 0; ks < 4; ks++) {
            unsigned a[2][4], b[8][2];
#pragma unroll
            for (int ma = 0; ma < 2; ma++) {
                int rb = wm + ma * 16;
                a[ma][0] = *(const unsigned*)&a_s[(rb + g) * ST + ks * 16 + 2 * t];
                a[ma][1] = *(const unsigned*)&a_s[(rb + g + 8) * ST + ks * 16 + 2 * t];
                a[ma][2] = *(const unsigned*)&a_s[(rb + g) * ST + ks * 16 + 2 * t + 8];
                a[ma][3] = *(const unsigned*)&a_s[(rb + g + 8) * ST + ks * 16 + 2 * t + 8];
            }
#pragma unroll
            for (int nb = 0; nb < 8; nb++) {
                int nr = wn + nb * 8 + g;
                b[nb][0] = *(const unsigned*)&b_s[nr * ST + ks * 16 + 2 * t];
                b[nb][1] = *(const unsigned*)&b_s[nr * ST + ks * 16 + 2 * t + 8];
            }
#pragma unroll
            for (int nb = 0; nb < 8; nb++)
#pragma unroll
                for (int ma = 0; ma < 2; ma++)
                    mma16(acc[ma][nb], a[ma], b[nb]);
        }
        __syncthreads();
    }

    // epilogue: +bias (scale for Q), head transpose; V stored transposed
    const float scale = (z == 0) ? SCL_F : 1.0f;
#pragma unroll
    for (int ma = 0; ma < 2; ma++)
#pragma unroll
        for (int nb = 0; nb < 8; nb++) {
            int c0 = n0 + wn + nb * 8 + 2 * t;
            float b0 = __ldg(&bias[c0]), b1 = __ldg(&bias[c0 + 1]);
            int h = c0 >> 6, d = c0 & 63;
#pragma unroll
            for (int rr = 0; rr < 2; rr++) {
                int r = m0 + wm + ma * 16 + g + rr * 8;
                int bb = r >> 11, ss = r & 2047;
                float vx = (acc[ma][nb][rr * 2 + 0] + b0) * scale;
                float vy = (acc[ma][nb][rr * 2 + 1] + b1) * scale;
                if (z != 2) {
                    *(unsigned*)&out[(((size_t)(bb * 16 + h)) * 2048 + ss) * 64 + d] =
                        h2pack(vx, vy);
                } else {
                    __half* vb = out + (size_t)(bb * 16 + h) * 64 * 2048;
                    vb[(size_t)d * 2048 + ss]       = __float2half_rn(vx);
                    vb[(size_t)(d + 1) * 2048 + ss] = __float2half_rn(vy);
                }
            }
        }
}

// ============================================================
// Kernel 2: FLASH ATTENTION fp16 — 4 warps x 32 Q-rows, 64-row KV
//   No P shuffles: S C-frag feeds fp16 A-frag natively.
// ============================================================
#define FLASH_SMEM ((128 * ST + 4 * 64 * ST) * 2)   /* 55296 bytes */

__global__ __launch_bounds__(128, 2) void flash_attn_kernel()
{
    extern __shared__ __half smh[];
    __half* Qs = smh;                                    // 128 x ST
    __half* Ks[2] = { smh + 128 * ST, smh + 128 * ST + 64 * ST };
    __half* Vs[2] = { smh + 128 * ST + 2 * 64 * ST, smh + 128 * ST + 3 * 64 * ST };

    const int bh = blockIdx.y;
    const int m0 = blockIdx.x * 128;
    const __half* Qp = Qh + (size_t)bh * SEQ * DEPTH;
    const __half* Kp = Kh + (size_t)bh * SEQ * DEPTH;
    const __half* Vp = Vh + (size_t)bh * DEPTH * SEQ;   // [d][s]
    __half* Op = Oh + (size_t)bh * SEQ * DEPTH;

    const int tid = threadIdx.x;
    const int warp = tid >> 5, lane = tid & 31;
    const int g = lane >> 2, t = lane & 3;
    const int wq0 = warp * 32;
    const unsigned FULL = 0xffffffffu;

    // Q tile 128x64 halves: 8 cp16 per thread
#pragma unroll
    for (int i = 0; i < 8; i++) {
        int id = tid + i * 128; int r = id >> 3, c = id & 7;
        cp16(su(&Qs[r * ST + c * 8]), Qp + (size_t)(m0 + r) * 64 + c * 8);
    }
    cpcommit();

#define KV_LOAD(buf, kv0)                                                         \
    do {                                                                          \
        _Pragma("unroll")                                                         \
        for (int i = 0; i < 4; i++) {                                             \
            int id = tid + i * 128; int r = id >> 3, c = id & 7;                  \
            cp16(su(&Ks[buf][r * ST + c * 8]),                                    \
                 Kp + (size_t)((kv0) + r) * 64 + c * 8);                          \
        }                                                                         \
        _Pragma("unroll")                                                         \
        for (int i = 0; i < 4; i++) {                                             \
            int id = tid + i * 128; int r = id >> 3, c = id & 7;                  \
            cp16(su(&Vs[buf][r * ST + c * 8]),                                    \
                 Vp + (size_t)r * 2048 + (kv0) + c * 8);                          \
        }                                                                         \
        cpcommit();                                                               \
    } while (0)

    KV_LOAD(0, 0);
    cpwait1();          // Q + nothing pending except tile0
    __syncthreads();

    float mr[4] = { -1e30f, -1e30f, -1e30f, -1e30f };
    float lr[4] = { 0.f, 0.f, 0.f, 0.f };
    float o[2][8][4] = {};

    for (int j = 0; j < 32; j++) {
        if (j + 1 < 32) { KV_LOAD((j + 1) & 1, (j + 1) * 64); cpwait1(); }
        else cpwait0();
        __syncthreads();
        const __half* ks = Ks[j & 1];
        const __half* vs = Vs[j & 1];

        // ---- S = Q K^T : warp tile 32 x 64, k16 steps ----
        float acc[2][8][4];
#pragma unroll
        for (int ma = 0; ma < 2; ma++)
#pragma unroll
            for (int nb = 0; nb < 8; nb++)
#pragma unroll
                for (int i = 0; i < 4; i++) acc[ma][nb][i] = 0.f;

#pragma unroll
        for (int kb = 0; kb < 4; kb++) {
            unsigned a[2][4];
#pragma unroll
            for (int ma = 0; ma < 2; ma++) {
                int rb = wq0 + ma * 16;
                a[ma][0] = *(const unsigned*)&Qs[(rb + g) * ST + kb * 16 + 2 * t];
                a[ma][1] = *(const unsigned*)&Qs[(rb + g + 8) * ST + kb * 16 + 2 * t];
                a[ma][2] = *(const unsigned*)&Qs[(rb + g) * ST + kb * 16 + 2 * t + 8];
                a[ma][3] = *(const unsigned*)&Qs[(rb + g + 8) * ST + kb * 16 + 2 * t + 8];
            }
#pragma unroll
            for (int nb = 0; nb < 8; nb++) {
                unsigned b[2];
                int nr = nb * 8 + g;
                b[0] = *(const unsigned*)&ks[nr * ST + kb * 16 + 2 * t];
                b[1] = *(const unsigned*)&ks[nr * ST + kb * 16 + 2 * t + 8];
                mma16(acc[0][nb], a[0], b);
                mma16(acc[1][nb], a[1], b);
            }
        }

        // ---- online softmax (log2 domain), 4 row-states ----
        float mx[4] = { -1e30f, -1e30f, -1e30f, -1e30f };
#pragma unroll
        for (int ma = 0; ma < 2; ma++)
#pragma unroll
            for (int nb = 0; nb < 8; nb++) {
                mx[ma * 2 + 0] = fmaxf(mx[ma * 2 + 0], fmaxf(acc[ma][nb][0], acc[ma][nb][1]));
                mx[ma * 2 + 1] = fmaxf(mx[ma * 2 + 1], fmaxf(acc[ma][nb][2], acc[ma][nb][3]));
            }
        float al[4];
#pragma unroll
        for (int s = 0; s < 4; s++) {
            mx[s] = fmaxf(mx[s], __shfl_xor_sync(FULL, mx[s], 1));
            mx[s] = fmaxf(mx[s], __shfl_xor_sync(FULL, mx[s], 2));
            float mn = fmaxf(mr[s], mx[s]);
            al[s] = ex2(mr[s] - mn);
            mr[s] = mn;
        }

        float sum[4] = { 0.f, 0.f, 0.f, 0.f };
#pragma unroll
        for (int ma = 0; ma < 2; ma++)
#pragma unroll
            for (int nb = 0; nb < 8; nb++) {
                float p0 = ex2(acc[ma][nb][0] - mr[ma * 2 + 0]);
                float p1 = ex2(acc[ma][nb][1] - mr[ma * 2 + 0]);
                float p2 = ex2(acc[ma][nb][2] - mr[ma * 2 + 1]);
                float p3 = ex2(acc[ma][nb][3] - mr[ma * 2 + 1]);
                sum[ma * 2 + 0] += p0 + p1;
                sum[ma * 2 + 1] += p2 + p3;
                acc[ma][nb][0] = p0; acc[ma][nb][1] = p1;
                acc[ma][nb][2] = p2; acc[ma][nb][3] = p3;
            }
#pragma unroll
        for (int s = 0; s < 4; s++) {
            sum[s] += __shfl_xor_sync(FULL, sum[s], 1);
            sum[s] += __shfl_xor_sync(FULL, sum[s], 2);
            lr[s] = lr[s] * al[s] + sum[s];
        }

#pragma unroll
        for (int ma = 0; ma < 2; ma++)
#pragma unroll
            for (int nb = 0; nb < 8; nb++) {
                o[ma][nb][0] *= al[ma * 2 + 0]; o[ma][nb][1] *= al[ma * 2 + 0];
                o[ma][nb][2] *= al[ma * 2 + 1]; o[ma][nb][3] *= al[ma * 2 + 1];
            }

        // ---- O += P @ V : C-frag packs directly into fp16 A-frag ----
#pragma unroll
        for (int kb = 0; kb < 4; kb++) {
            unsigned ap[2][4];
#pragma unroll
            for (int ma = 0; ma < 2; ma++) {
                ap[ma][0] = h2pack(acc[ma][2 * kb][0],     acc[ma][2 * kb][1]);
                ap[ma][1] = h2pack(acc[ma][2 * kb][2],     acc[ma][2 * kb][3]);
                ap[ma][2] = h2pack(acc[ma][2 * kb + 1][0], acc[ma][2 * kb + 1][1]);
                ap[ma][3] = h2pack(acc[ma][2 * kb + 1][2], acc[ma][2 * kb + 1][3]);
            }
#pragma unroll
            for (int nb = 0; nb < 8; nb++) {
                unsigned b[2];
                int nr = nb * 8 + g;   // depth index
                b[0] = *(const unsigned*)&vs[nr * ST + kb * 16 + 2 * t];
                b[1] = *(const unsigned*)&vs[nr * ST + kb * 16 + 2 * t + 8];
                mma16(o[0][nb], ap[0], b);
                mma16(o[1][nb], ap[1], b);
            }
        }
        __syncthreads();
    }

    // ---- epilogue: O /= l, fp16 store ----
    float inv[4];
#pragma unroll
    for (int s = 0; s < 4; s++) inv[s] = 1.f / lr[s];
#pragma unroll
    for (int ma = 0; ma < 2; ma++)
#pragma unroll
        for (int nb = 0; nb < 8; nb++) {
            int c0 = nb * 8 + 2 * t;
            {
                int r = m0 + wq0 + ma * 16 + g;
                *(unsigned*)&Op[(size_t)r * 64 + c0] =
                    h2pack(o[ma][nb][0] * inv[ma * 2 + 0], o[ma][nb][1] * inv[ma * 2 + 0]);
            }
            {
                int r = m0 + wq0 + ma * 16 + g + 8;
                *(unsigned*)&Op[(size_t)r * 64 + c0] =
                    h2pack(o[ma][nb][2] * inv[ma * 2 + 1], o[ma][nb][3] * inv[ma * 2 + 1]);
            }
        }
}

// ============================================================
// Kernel 3: out = untranspose(Oh) @ wo + bo, fp16 mma, fp32 out
// ============================================================
__global__ __launch_bounds__(256, 2) void outproj_kernel(
    const __half* __restrict__ W, const float* __restrict__ bo,
    float* __restrict__ out)
{
    extern __shared__ __half smh[];
    __half* Ah[2] = { smh, smh + 128 * ST };
    __half* Bh[2] = { smh + 2 * 128 * ST, smh + 3 * 128 * ST };

    const int tid = threadIdx.x;
    const int m0 = blockIdx.y * 128, n0 = blockIdx.x * 128;
    const int warp = tid >> 5, lane = tid & 31;
    const int g = lane >> 2, t = lane & 3;
    const int wm = (warp & 3) * 32, wn = (warp >> 2) * 64;

    float acc[2][8][4] = {};

#define OP_LOAD(buf, k0)                                                          \
    do {                                                                          \
        _Pragma("unroll")                                                         \
        for (int i = 0; i < 4; i++) {                                             \
            int id = tid + i * 256; int r = id >> 3, cc = id & 7;                 \
            int m = m0 + r; int k = (k0) + cc * 8;                                \
            const __half* src = Oh + (((size_t)((m >> 11) * 16 + (k >> 6))) * 2048 \
                                      + (m & 2047)) * 64 + (k & 63);              \
            cp16(su(&Ah[buf][r * ST + cc * 8]), src);                             \
        }                                                                         \
        _Pragma("unroll")                                                         \
        for (int i = 0; i < 4; i++) {                                             \
            int id = tid + i * 256; int r = id >> 3, cc = id & 7;                 \
            cp16(su(&Bh[buf][r * ST + cc * 8]),                                   \
                 W + (size_t)(n0 + r) * 1024 + (k0) + cc * 8);                    \
        }                                                                         \
        cpcommit();                                                               \
    } while (0)

    OP_LOAD(0, 0);
    for (int it = 0; it < 16; it++) {
        if (it + 1 < 16) { OP_LOAD((it + 1) & 1, (it + 1) * 64); cpwait1(); }
        else cpwait0();
        __syncthreads();
        const __half* a_s = Ah[it & 1];
        const __half* b_s = Bh[it & 1];
#pragma unroll
        for (int ks = 0; ks < 4; ks++) {
            unsigned a[2][4], b[8][2];
#pragma unroll
            for (int ma = 0; ma < 2; ma++) {
                int rb = wm + ma * 16;
                a[ma][0] = *(const unsigned*)&a_s[(rb + g) * ST + ks * 16 + 2 * t];
                a[ma][1] = *(const unsigned*)&a_s[(rb + g + 8) * ST + ks * 16 + 2 * t];
                a[ma][2] = *(const unsigned*)&a_s[(rb + g) * ST + ks * 16 + 2 * t + 8];
                a[ma][3] = *(const unsigned*)&a_s[(rb + g + 8) * ST + ks * 16 + 2 * t + 8];
            }
#pragma unroll
            for (int nb = 0; nb < 8; nb++) {
                int nr = wn + nb * 8 + g;
                b[nb][0] = *(const unsigned*)&b_s[nr * ST + ks * 16 + 2 * t];
                b[nb][1] = *(const unsigned*)&b_s[nr * ST + ks * 16 + 2 * t + 8];
            }
#pragma unroll
            for (int nb = 0; nb < 8; nb++)
#pragma unroll
                for (int ma = 0; ma < 2; ma++)
                    mma16(acc[ma][nb], a[ma], b[nb]);
        }
        __syncthreads();
    }

#pragma unroll
    for (int ma = 0; ma < 2; ma++)
#pragma unroll
        for (int nb = 0; nb < 8; nb++) {
            int c0 = n0 + wn + nb * 8 + 2 * t;
            float b0 = __ldg(&bo[c0]), b1 = __ldg(&bo[c0 + 1]);
#pragma unroll
            for (int rr = 0; rr < 2; rr++) {
                int r = m0 + wm + ma * 16 + g + rr * 8;
                float2 v;
                v.x = acc[ma][nb][rr * 2 + 0] + b0;
                v.y = acc[ma][nb][rr * 2 + 1] + b1;
                *(float2*)&out[(size_t)r * 1024 + c0] = v;
            }
        }
}

// ============================================================
extern "C" void kernel_launch(void* const* d_in, const int* in_sizes, int n_in,
                              void* d_out, int out_size)
{
    const float* x  = (const float*)d_in[0];
    const float* wq = (const float*)d_in[1];
    const float* bq = (const float*)d_in[2];
    const float* wk = (const float*)d_in[3];
    const float* bk = (const float*)d_in[4];
    const float* wv = (const float*)d_in[5];
    const float* bv = (const float*)d_in[6];
    const float* wo = (const float*)d_in[7];
    const float* bo = (const float*)d_in[8];
    float* out = (float*)d_out;

    cudaFuncSetAttribute(proj_qkv_kernel,   cudaFuncAttributeMaxDynamicSharedMemorySize, GEMM_SMEM);
    cudaFuncSetAttribute(flash_attn_kernel, cudaFuncAttributeMaxDynamicSharedMemorySize, FLASH_SMEM);
    cudaFuncSetAttribute(outproj_kernel,    cudaFuncAttributeMaxDynamicSharedMemorySize, GEMM_SMEM);

    __half* Xh_p;  cudaGetSymbolAddress((void**)&Xh_p, Xh);
    __half* Wt_p;  cudaGetSymbolAddress((void**)&Wt_p, Wth);
    __half* Qp;    cudaGetSymbolAddress((void**)&Qp, Qh);
    __half* Kp;    cudaGetSymbolAddress((void**)&Kp, Kh);
    __half* Vp;    cudaGetSymbolAddress((void**)&Vp, Vh);

    static __half* h_tab[3];
    h_tab[0] = Qp; h_tab[1] = Kp; h_tab[2] = Vp;
    void* tab_dev; cudaGetSymbolAddress(&tab_dev, QKVout16);
    cudaMemcpyAsync(tab_dev, h_tab, sizeof(h_tab), cudaMemcpyHostToDevice);

    dim3 blk(256);
    const size_t WSZ = (size_t)D_MODEL * D_MODEL;

    {
        int n4 = (MROWS * D_MODEL) / 4;
        cvt_x_kernel<<<(n4 + 255) / 256, blk>>>(x, Xh_p, n4);
        cvt_wT_kernel<<<dim3(32, 32, 4), dim3(32, 8)>>>(wq, wk, wv, wo, Wt_p);
    }

    // merged QKV (grid.z selects projection)
    dim3 gqkv(D_MODEL / 128, MROWS / 128, 3);
    proj_qkv_kernel<<<gqkv, blk, GEMM_SMEM>>>(Xh_p, Wt_p, bq, bk, bv);

    flash_attn_kernel<<<dim3(SEQ / 128, BH), dim3(128), FLASH_SMEM>>>();

    outproj_kernel<<<dim3(D_MODEL / 128, MROWS / 128), blk, GEMM_SMEM>>>(
        Wt_p + 3 * WSZ, bo, out);
}

// round 12
// speedup vs baseline: 2.1767x; 1.0065x over previous
#include <cuda_runtime.h>
#include <cuda_fp16.h>

#define D_MODEL 1024
#define HEADS   16
#define DEPTH   64
#define BATCH   4
#define SEQ     2048
#define MROWS   (BATCH * SEQ)   /* 8192 */
#define BH      (BATCH * HEADS) /* 64   */

// ---- static scratch (allocation-free per harness rules) ----
__device__ __half Xh[(size_t)MROWS * D_MODEL];        // x in fp16
__device__ __half Wth[(size_t)4 * D_MODEL * D_MODEL]; // W^T fp16: [4][n][k]
__device__ __half Qh[(size_t)BH * SEQ * DEPTH];       // [bh][s][d], pre-scaled
__device__ __half Kh[(size_t)BH * SEQ * DEPTH];       // [bh][s][d]
__device__ __half Vh[(size_t)BH * DEPTH * SEQ];       // TRANSPOSED [bh][d][s]
__device__ __half Oh[(size_t)BH * SEQ * DEPTH];       // [bh][s][d]

__device__ __half* QKVout16[3];

#define SCL_F (0.125f * 1.4426950408889634f)   /* 1/sqrt(64) * log2(e) */

// ---------------- helpers ----------------
__device__ __forceinline__ unsigned su(const void* p) {
    return (unsigned)__cvta_generic_to_shared(p);
}
__device__ __forceinline__ void cp16(unsigned d, const void* s) {
    asm volatile("cp.async.cg.shared.global [%0], [%1], 16;" :: "r"(d), "l"(s));
}
__device__ __forceinline__ void cpcommit() { asm volatile("cp.async.commit_group;"); }
__device__ __forceinline__ void cpwait0() { asm volatile("cp.async.wait_group 0;"); }
__device__ __forceinline__ void cpwait1() { asm volatile("cp.async.wait_group 1;"); }

// pack two floats -> half2 (x = low element, y = high element)
__device__ __forceinline__ unsigned h2pack(float x, float y) {
    unsigned r;
    asm("cvt.rn.f16x2.f32 %0, %1, %2;" : "=r"(r) : "f"(y), "f"(x));
    return r;
}
__device__ __forceinline__ unsigned h2u(__half2 h) { return *(unsigned*)&h; }
__device__ __forceinline__ __half2 u2h(unsigned u) { return *(__half2*)&u; }

// fp16 mma m16n8k16, fp32 accumulate
__device__ __forceinline__ void mma16(float* c, const unsigned* a, const unsigned* b) {
    asm volatile(
        "mma.sync.aligned.m16n8k16.row.col.f32.f16.f16.f32 "
        "{%0,%1,%2,%3},{%4,%5,%6,%7},{%8,%9},{%0,%1,%2,%3};"
        : "+f"(c[0]), "+f"(c[1]), "+f"(c[2]), "+f"(c[3])
        : "r"(a[0]), "r"(a[1]), "r"(a[2]), "r"(a[3]), "r"(b[0]), "r"(b[1]));
}

#define ST 72   /* smem row stride in halves = 144 bytes */

// ---------------- prep: x -> fp16 ----------------
__global__ __launch_bounds__(256) void cvt_x_kernel(
    const float* __restrict__ in, __half* __restrict__ out, int n4)
{
    int i = blockIdx.x * 256 + threadIdx.x;
    if (i < n4) {
        float4 v = ((const float4*)in)[i];
        uint2 o;
        o.x = h2pack(v.x, v.y);
        o.y = h2pack(v.z, v.w);
        ((uint2*)out)[i] = o;
    }
}

// ---------------- prep: transpose weights -> fp16  Wth[z][n][k] ----------------
__global__ __launch_bounds__(256) void cvt_wT_kernel(
    const float* __restrict__ w0, const float* __restrict__ w1,
    const float* __restrict__ w2, const float* __restrict__ w3,
    __half* __restrict__ out)
{
    __shared__ float t[32][33];
    const float* src = (blockIdx.z == 0) ? w0 : (blockIdx.z == 1) ? w1
                       : (blockIdx.z == 2) ? w2 : w3;
    __half* dst = out + (size_t)blockIdx.z * (size_t)D_MODEL * D_MODEL;
    int bx = blockIdx.x * 32;   // k tile
    int by = blockIdx.y * 32;   // n tile
#pragma unroll
    for (int j = 0; j < 4; j++)
        t[threadIdx.y + j * 8][threadIdx.x] =
            src[(size_t)(bx + threadIdx.y + j * 8) * D_MODEL + by + threadIdx.x];
    __syncthreads();
#pragma unroll
    for (int j = 0; j < 4; j++)
        dst[(size_t)(by + threadIdx.y + j * 8) * D_MODEL + bx + threadIdx.x] =
            __float2half_rn(t[threadIdx.x][threadIdx.y + j * 8]);
}

// ============================================================
// Kernel 1: MERGED QKV proj, fp16 m16n8k16 (unchanged from R11)
// ============================================================
#define GEMM_SMEM (4 * 128 * ST * 2)   /* 73728 bytes */

__global__ __launch_bounds__(256, 2) void proj_qkv_kernel(
    const __half* __restrict__ A, const __half* __restrict__ Wbase,
    const float* __restrict__ bq, const float* __restrict__ bk,
    const float* __restrict__ bv)
{
    extern __shared__ __half smh[];
    __half* Ah[2] = { smh, smh + 128 * ST };
    __half* Bh[2] = { smh + 2 * 128 * ST, smh + 3 * 128 * ST };

    const int z = blockIdx.z;
    const __half* W = Wbase + (size_t)z * D_MODEL * D_MODEL;
    const float* bias = (z == 0) ? bq : (z == 1) ? bk : bv;
    __half* out = QKVout16[z];

    const int tid = threadIdx.x;
    const int m0 = blockIdx.y * 128, n0 = blockIdx.x * 128;
    const int warp = tid >> 5, lane = tid & 31;
    const int g = lane >> 2, t = lane & 3;
    const int wm = (warp & 3) * 32, wn = (warp >> 2) * 64;

    float acc[2][8][4] = {};

#define PROJ_LOAD(buf, k0)                                                        \
    do {                                                                          \
        _Pragma("unroll")                                                         \
        for (int i = 0; i < 4; i++) {                                             \
            int id = tid + i * 256; int r = id >> 3, cc = id & 7;                 \
            cp16(su(&Ah[buf][r * ST + cc * 8]),                                   \
                 A + (size_t)(m0 + r) * 1024 + (k0) + cc * 8);                    \
        }                                                                         \
        _Pragma("unroll")                                                         \
        for (int i = 0; i < 4; i++) {                                             \
            int id = tid + i * 256; int r = id >> 3, cc = id & 7;                 \
            cp16(su(&Bh[buf][r * ST + cc * 8]),                                   \
                 W + (size_t)(n0 + r) * 1024 + (k0) + cc * 8);                    \
        }                                                                         \
        cpcommit();                                                               \
    } while (0)

    PROJ_LOAD(0, 0);
    for (int it = 0; it < 16; it++) {
        if (it + 1 < 16) { PROJ_LOAD((it + 1) & 1, (it + 1) * 64); cpwait1(); }
        else cpwait0();
        __syncthreads();
        const __half* a_s = Ah[it & 1];
        const __half* b_s = Bh[it & 1];
#pragma unroll
        for (int ks = 0; ks < 4; ks++) {
            unsigned a[2][4], b[8][2];
#pragma unroll
            for (int ma = 0; ma < 2; ma++) {
                int rb = wm + ma * 16;
                a[ma][0] = *(const unsigned*)&a_s[(rb + g) * ST + ks * 16 + 2 * t];
                a[ma][1] = *(const unsigned*)&a_s[(rb + g + 8) * ST + ks * 16 + 2 * t];
                a[ma][2] = *(const unsigned*)&a_s[(rb + g) * ST + ks * 16 + 2 * t + 8];
                a[ma][3] = *(const unsigned*)&a_s[(rb + g + 8) * ST + ks * 16 + 2 * t + 8];
            }
#pragma unroll
            for (int nb = 0; nb < 8; nb++) {
                int nr = wn + nb * 8 + g;
                b[nb][0] = *(const unsigned*)&b_s[nr * ST + ks * 16 + 2 * t];
                b[nb][1] = *(const unsigned*)&b_s[nr * ST + ks * 16 + 2 * t + 8];
            }
#pragma unroll
            for (int nb = 0; nb < 8; nb++)
#pragma unroll
                for (int ma = 0; ma < 2; ma++)
                    mma16(acc[ma][nb], a[ma], b[nb]);
        }
        __syncthreads();
    }

    const float scale = (z == 0) ? SCL_F : 1.0f;
#pragma unroll
    for (int ma = 0; ma < 2; ma++)
#pragma unroll
        for (int nb = 0; nb < 8; nb++) {
            int c0 = n0 + wn + nb * 8 + 2 * t;
            float b0 = __ldg(&bias[c0]), b1 = __ldg(&bias[c0 + 1]);
            int h = c0 >> 6, d = c0 & 63;
#pragma unroll
            for (int rr = 0; rr < 2; rr++) {
                int r = m0 + wm + ma * 16 + g + rr * 8;
                int bb = r >> 11, ss = r & 2047;
                float vx = (acc[ma][nb][rr * 2 + 0] + b0) * scale;
                float vy = (acc[ma][nb][rr * 2 + 1] + b1) * scale;
                if (z != 2) {
                    *(unsigned*)&out[(((size_t)(bb * 16 + h)) * 2048 + ss) * 64 + d] =
                        h2pack(vx, vy);
                } else {
                    __half* vb = out + (size_t)(bb * 16 + h) * 64 * 2048;
                    vb[(size_t)d * 2048 + ss]       = __float2half_rn(vx);
                    vb[(size_t)(d + 1) * 2048 + ss] = __float2half_rn(vy);
                }
            }
        }
}

// ============================================================
// Kernel 2: FLASH ATTENTION fp16 — half2 softmax + ones-column l
// ============================================================
#define FLASH_SMEM ((128 * ST + 4 * 64 * ST) * 2)   /* 55296 bytes */
#define ONES2 0x3C003C00u                            /* half2(1,1) */

__global__ __launch_bounds__(128, 2) void flash_attn_kernel()
{
    extern __shared__ __half smh[];
    __half* Qs = smh;                                    // 128 x ST
    __half* Ks[2] = { smh + 128 * ST, smh + 128 * ST + 64 * ST };
    __half* Vs[2] = { smh + 128 * ST + 2 * 64 * ST, smh + 128 * ST + 3 * 64 * ST };

    const int bh = blockIdx.y;
    const int m0 = blockIdx.x * 128;
    const __half* Qp = Qh + (size_t)bh * SEQ * DEPTH;
    const __half* Kp = Kh + (size_t)bh * SEQ * DEPTH;
    const __half* Vp = Vh + (size_t)bh * DEPTH * SEQ;   // [d][s]
    __half* Op = Oh + (size_t)bh * SEQ * DEPTH;

    const int tid = threadIdx.x;
    const int warp = tid >> 5, lane = tid & 31;
    const int g = lane >> 2, t = lane & 3;
    const int wq0 = warp * 32;
    const unsigned FULL = 0xffffffffu;

#pragma unroll
    for (int i = 0; i < 8; i++) {
        int id = tid + i * 128; int r = id >> 3, c = id & 7;
        cp16(su(&Qs[r * ST + c * 8]), Qp + (size_t)(m0 + r) * 64 + c * 8);
    }
    cpcommit();

#define KV_LOAD(buf, kv0)                                                         \
    do {                                                                          \
        _Pragma("unroll")                                                         \
        for (int i = 0; i < 4; i++) {                                             \
            int id = tid + i * 128; int r = id >> 3, c = id & 7;                  \
            cp16(su(&Ks[buf][r * ST + c * 8]),                                    \
                 Kp + (size_t)((kv0) + r) * 64 + c * 8);                          \
        }                                                                         \
        _Pragma("unroll")                                                         \
        for (int i = 0; i < 4; i++) {                                             \
            int id = tid + i * 128; int r = id >> 3, c = id & 7;                  \
            cp16(su(&Vs[buf][r * ST + c * 8]),                                    \
                 Vp + (size_t)r * 2048 + (kv0) + c * 8);                          \
        }                                                                         \
        cpcommit();                                                               \
    } while (0)

    KV_LOAD(0, 0);
    cpwait1();
    __syncthreads();

    // running max per ma: half2(lo = row g, hi = row g+8)
    __half2 mr2[2];
    mr2[0] = __float2half2_rn(-60000.f);
    mr2[1] = __float2half2_rn(-60000.f);

    // o[ma][0..7] = output cols; o[ma][8] = row-sum column (l)
    float o[2][9][4] = {};

    for (int j = 0; j < 32; j++) {
        if (j + 1 < 32) { KV_LOAD((j + 1) & 1, (j + 1) * 64); cpwait1(); }
        else cpwait0();
        __syncthreads();
        const __half* ks = Ks[j & 1];
        const __half* vs = Vs[j & 1];

        // ---- S = Q K^T : warp tile 32 x 64, k16 steps ----
        float acc[2][8][4];
#pragma unroll
        for (int ma = 0; ma < 2; ma++)
#pragma unroll
            for (int nb = 0; nb < 8; nb++)
#pragma unroll
                for (int i = 0; i < 4; i++) acc[ma][nb][i] = 0.f;

#pragma unroll
        for (int kb = 0; kb < 4; kb++) {
            unsigned a[2][4];
#pragma unroll
            for (int ma = 0; ma < 2; ma++) {
                int rb = wq0 + ma * 16;
                a[ma][0] = *(const unsigned*)&Qs[(rb + g) * ST + kb * 16 + 2 * t];
                a[ma][1] = *(const unsigned*)&Qs[(rb + g + 8) * ST + kb * 16 + 2 * t];
                a[ma][2] = *(const unsigned*)&Qs[(rb + g) * ST + kb * 16 + 2 * t + 8];
                a[ma][3] = *(const unsigned*)&Qs[(rb + g + 8) * ST + kb * 16 + 2 * t + 8];
            }
#pragma unroll
            for (int nb = 0; nb < 8; nb++) {
                unsigned b[2];
                int nr = nb * 8 + g;
                b[0] = *(const unsigned*)&ks[nr * ST + kb * 16 + 2 * t];
                b[1] = *(const unsigned*)&ks[nr * ST + kb * 16 + 2 * t + 8];
                mma16(acc[0][nb], a[0], b);
                mma16(acc[1][nb], a[1], b);
            }
        }

        // ---- pack scores to half2: pr[ma][0][nb]=row g, pr[ma][1][nb]=row g+8 ----
        __half2 pr[2][2][8];
#pragma unroll
        for (int ma = 0; ma < 2; ma++)
#pragma unroll
            for (int nb = 0; nb < 8; nb++) {
                pr[ma][0][nb] = u2h(h2pack(acc[ma][nb][0], acc[ma][nb][1]));
                pr[ma][1][nb] = u2h(h2pack(acc[ma][nb][2], acc[ma][nb][3]));
            }

        // ---- max reduction in half2 domain ----
        float al[4];
#pragma unroll
        for (int ma = 0; ma < 2; ma++) {
            __half2 x0 = pr[ma][0][0], x1 = pr[ma][1][0];
#pragma unroll
            for (int nb = 1; nb < 8; nb++) {
                x0 = __hmax2(x0, pr[ma][0][nb]);
                x1 = __hmax2(x1, pr[ma][1][nb]);
            }
            __half2 mm = __halves2half2(
                __hmax(__low2half(x0), __high2half(x0)),
                __hmax(__low2half(x1), __high2half(x1)));
            // cross-quad max (both rows ride in one half2)
            mm = __hmax2(mm, u2h(__shfl_xor_sync(FULL, h2u(mm), 1)));
            mm = __hmax2(mm, u2h(__shfl_xor_sync(FULL, h2u(mm), 2)));
            __half2 nm = __hmax2(mr2[ma], mm);
            __half2 a2 = h2exp2(__hsub2(mr2[ma], nm));
            mr2[ma] = nm;
            al[ma * 2 + 0] = __low2float(a2);
            al[ma * 2 + 1] = __high2float(a2);
        }

        // ---- rescale O (incl. the l column) ----
#pragma unroll
        for (int ma = 0; ma < 2; ma++)
#pragma unroll
            for (int nb = 0; nb < 9; nb++) {
                o[ma][nb][0] *= al[ma * 2 + 0]; o[ma][nb][1] *= al[ma * 2 + 0];
                o[ma][nb][2] *= al[ma * 2 + 1]; o[ma][nb][3] *= al[ma * 2 + 1];
            }

        // ---- O += P @ V, P computed on the fly; nb==8 = ones column (l) ----
#pragma unroll
        for (int kb = 0; kb < 4; kb++) {
            unsigned ap[2][4];
#pragma unroll
            for (int ma = 0; ma < 2; ma++) {
                __half2 m0b = __low2half2(mr2[ma]);
                __half2 m1b = __high2half2(mr2[ma]);
                ap[ma][0] = h2u(h2exp2(__hsub2(pr[ma][0][2 * kb],     m0b)));
                ap[ma][1] = h2u(h2exp2(__hsub2(pr[ma][1][2 * kb],     m1b)));
                ap[ma][2] = h2u(h2exp2(__hsub2(pr[ma][0][2 * kb + 1], m0b)));
                ap[ma][3] = h2u(h2exp2(__hsub2(pr[ma][1][2 * kb + 1], m1b)));
            }
#pragma unroll
            for (int nb = 0; nb < 9; nb++) {
                unsigned b[2];
                if (nb < 8) {
                    int nr = nb * 8 + g;
                    b[0] = *(const unsigned*)&vs[nr * ST + kb * 16 + 2 * t];
                    b[1] = *(const unsigned*)&vs[nr * ST + kb * 16 + 2 * t + 8];
                } else {
                    b[0] = ONES2; b[1] = ONES2;
                }
                mma16(o[0][nb], ap[0], b);
                mma16(o[1][nb], ap[1], b);
            }
        }
        __syncthreads();
    }

    // ---- epilogue: O /= l (from ones column), fp16 store ----
#pragma unroll
    for (int ma = 0; ma < 2; ma++) {
        float inv0 = 1.f / o[ma][8][0];
        float inv1 = 1.f / o[ma][8][2];
#pragma unroll
        for (int nb = 0; nb < 8; nb++) {
            int c0 = nb * 8 + 2 * t;
            {
                int r = m0 + wq0 + ma * 16 + g;
                *(unsigned*)&Op[(size_t)r * 64 + c0] =
                    h2pack(o[ma][nb][0] * inv0, o[ma][nb][1] * inv0);
            }
            {
                int r = m0 + wq0 + ma * 16 + g + 8;
                *(unsigned*)&Op[(size_t)r * 64 + c0] =
                    h2pack(o[ma][nb][2] * inv1, o[ma][nb][3] * inv1);
            }
        }
    }
}

// ============================================================
// Kernel 3: out = untranspose(Oh) @ wo + bo, fp16 mma, fp32 out
// ============================================================
__global__ __launch_bounds__(256, 2) void outproj_kernel(
    const __half* __restrict__ W, const float* __restrict__ bo,
    float* __restrict__ out)
{
    extern __shared__ __half smh[];
    __half* Ah[2] = { smh, smh + 128 * ST };
    __half* Bh[2] = { smh + 2 * 128 * ST, smh + 3 * 128 * ST };

    const int tid = threadIdx.x;
    const int m0 = blockIdx.y * 128, n0 = blockIdx.x * 128;
    const int warp = tid >> 5, lane = tid & 31;
    const int g = lane >> 2, t = lane & 3;
    const int wm = (warp & 3) * 32, wn = (warp >> 2) * 64;

    float acc[2][8][4] = {};

#define OP_LOAD(buf, k0)                                                          \
    do {                                                                          \
        _Pragma("unroll")                                                         \
        for (int i = 0; i < 4; i++) {                                             \
            int id = tid + i * 256; int r = id >> 3, cc = id & 7;                 \
            int m = m0 + r; int k = (k0) + cc * 8;                                \
            const __half* src = Oh + (((size_t)((m >> 11) * 16 + (k >> 6))) * 2048 \
                                      + (m & 2047)) * 64 + (k & 63);              \
            cp16(su(&Ah[buf][r * ST + cc * 8]), src);                             \
        }                                                                         \
        _Pragma("unroll")                                                         \
        for (int i = 0; i < 4; i++) {                                             \
            int id = tid + i * 256; int r = id >> 3, cc = id & 7;                 \
            cp16(su(&Bh[buf][r * ST + cc * 8]),                                   \
                 W + (size_t)(n0 + r) * 1024 + (k0) + cc * 8);                    \
        }                                                                         \
        cpcommit();                                                               \
    } while (0)

    OP_LOAD(0, 0);
    for (int it = 0; it < 16; it++) {
        if (it + 1 < 16) { OP_LOAD((it + 1) & 1, (it + 1) * 64); cpwait1(); }
        else cpwait0();
        __syncthreads();
        const __half* a_s = Ah[it & 1];
        const __half* b_s = Bh[it & 1];
#pragma unroll
        for (int ks = 0; ks < 4; ks++) {
            unsigned a[2][4], b[8][2];
#pragma unroll
            for (int ma = 0; ma < 2; ma++) {
                int rb = wm + ma * 16;
                a[ma][0] = *(const unsigned*)&a_s[(rb + g) * ST + ks * 16 + 2 * t];
                a[ma][1] = *(const unsigned*)&a_s[(rb + g + 8) * ST + ks * 16 + 2 * t];
                a[ma][2] = *(const unsigned*)&a_s[(rb + g) * ST + ks * 16 + 2 * t + 8];
                a[ma][3] = *(const unsigned*)&a_s[(rb + g + 8) * ST + ks * 16 + 2 * t + 8];
            }
#pragma unroll
            for (int nb = 0; nb < 8; nb++) {
                int nr = wn + nb * 8 + g;
                b[nb][0] = *(const unsigned*)&b_s[nr * ST + ks * 16 + 2 * t];
                b[nb][1] = *(const unsigned*)&b_s[nr * ST + ks * 16 + 2 * t + 8];
            }
#pragma unroll
            for (int nb = 0; nb < 8; nb++)
#pragma unroll
                for (int ma = 0; ma < 2; ma++)
                    mma16(acc[ma][nb], a[ma], b[nb]);
        }
        __syncthreads();
    }

#pragma unroll
    for (int ma = 0; ma < 2; ma++)
#pragma unroll
        for (int nb = 0; nb < 8; nb++) {
            int c0 = n0 + wn + nb * 8 + 2 * t;
            float b0 = __ldg(&bo[c0]), b1 = __ldg(&bo[c0 + 1]);
#pragma unroll
            for (int rr = 0; rr < 2; rr++) {
                int r = m0 + wm + ma * 16 + g + rr * 8;
                float2 v;
                v.x = acc[ma][nb][rr * 2 + 0] + b0;
                v.y = acc[ma][nb][rr * 2 + 1] + b1;
                *(float2*)&out[(size_t)r * 1024 + c0] = v;
            }
        }
}

// ============================================================
extern "C" void kernel_launch(void* const* d_in, const int* in_sizes, int n_in,
                              void* d_out, int out_size)
{
    const float* x  = (const float*)d_in[0];
    const float* wq = (const float*)d_in[1];
    const float* bq = (const float*)d_in[2];
    const float* wk = (const float*)d_in[3];
    const float* bk = (const float*)d_in[4];
    const float* wv = (const float*)d_in[5];
    const float* bv = (const float*)d_in[6];
    const float* wo = (const float*)d_in[7];
    const float* bo = (const float*)d_in[8];
    float* out = (float*)d_out;

    cudaFuncSetAttribute(proj_qkv_kernel,   cudaFuncAttributeMaxDynamicSharedMemorySize, GEMM_SMEM);
    cudaFuncSetAttribute(flash_attn_kernel, cudaFuncAttributeMaxDynamicSharedMemorySize, FLASH_SMEM);
    cudaFuncSetAttribute(outproj_kernel,    cudaFuncAttributeMaxDynamicSharedMemorySize, GEMM_SMEM);

    __half* Xh_p;  cudaGetSymbolAddress((void**)&Xh_p, Xh);
    __half* Wt_p;  cudaGetSymbolAddress((void**)&Wt_p, Wth);
    __half* Qp;    cudaGetSymbolAddress((void**)&Qp, Qh);
    __half* Kp;    cudaGetSymbolAddress((void**)&Kp, Kh);
    __half* Vp;    cudaGetSymbolAddress((void**)&Vp, Vh);

    static __half* h_tab[3];
    h_tab[0] = Qp; h_tab[1] = Kp; h_tab[2] = Vp;
    void* tab_dev; cudaGetSymbolAddress(&tab_dev, QKVout16);
    cudaMemcpyAsync(tab_dev, h_tab, sizeof(h_tab), cudaMemcpyHostToDevice);

    dim3 blk(256);
    const size_t WSZ = (size_t)D_MODEL * D_MODEL;

    {
        int n4 = (MROWS * D_MODEL) / 4;
        cvt_x_kernel<<<(n4 + 255) / 256, blk>>>(x, Xh_p, n4);
        cvt_wT_kernel<<<dim3(32, 32, 4), dim3(32, 8)>>>(wq, wk, wv, wo, Wt_p);
    }

    dim3 gqkv(D_MODEL / 128, MROWS / 128, 3);
    proj_qkv_kernel<<<gqkv, blk, GEMM_SMEM>>>(Xh_p, Wt_p, bq, bk, bv);

    flash_attn_kernel<<<dim3(SEQ / 128, BH), dim3(128), FLASH_SMEM>>>();

    outproj_kernel<<<dim3(D_MODEL / 128, MROWS / 128), blk, GEMM_SMEM>>>(
        Wt_p + 3 * WSZ, bo, out);
}

// round 13
// speedup vs baseline: 2.2507x; 1.0340x over previous
#include <cuda_runtime.h>
#include <cuda_fp16.h>

#define D_MODEL 1024
#define HEADS   16
#define DEPTH   64
#define BATCH   4
#define SEQ     2048
#define MROWS   (BATCH * SEQ)   /* 8192 */
#define BH      (BATCH * HEADS) /* 64   */

// ---- static scratch (allocation-free per harness rules) ----
__device__ __half Xh[(size_t)MROWS * D_MODEL];        // x in fp16
__device__ __half Wth[(size_t)4 * D_MODEL * D_MODEL]; // W^T fp16: [4][n][k]
__device__ __half Qh[(size_t)BH * SEQ * DEPTH];       // [bh][s][d], pre-scaled
__device__ __half Kh[(size_t)BH * SEQ * DEPTH];       // [bh][s][d]
__device__ __half Vh[(size_t)BH * DEPTH * SEQ];       // TRANSPOSED [bh][d][s]
__device__ __half Oh[(size_t)BH * SEQ * DEPTH];       // [bh][s][d]

__device__ __half* QKVout16[3];

#define SCL_F (0.125f * 1.4426950408889634f)   /* 1/sqrt(64) * log2(e) */

// ---------------- helpers ----------------
__device__ __forceinline__ unsigned su(const void* p) {
    return (unsigned)__cvta_generic_to_shared(p);
}
__device__ __forceinline__ void cp16(unsigned d, const void* s) {
    asm volatile("cp.async.cg.shared.global [%0], [%1], 16;" :: "r"(d), "l"(s));
}
__device__ __forceinline__ void cpcommit() { asm volatile("cp.async.commit_group;"); }
__device__ __forceinline__ void cpwait0() { asm volatile("cp.async.wait_group 0;"); }
__device__ __forceinline__ void cpwait1() { asm volatile("cp.async.wait_group 1;"); }

// pack two floats -> half2 (x = low element, y = high element)
__device__ __forceinline__ unsigned h2pack(float x, float y) {
    unsigned r;
    asm("cvt.rn.f16x2.f32 %0, %1, %2;" : "=r"(r) : "f"(y), "f"(x));
    return r;
}
__device__ __forceinline__ unsigned h2u(__half2 h) { return *(unsigned*)&h; }
__device__ __forceinline__ __half2 u2h(unsigned u) { return *(__half2*)&u; }

// fp16 mma m16n8k16, fp32 accumulate
__device__ __forceinline__ void mma16(float* c, const unsigned* a, const unsigned* b) {
    asm volatile(
        "mma.sync.aligned.m16n8k16.row.col.f32.f16.f16.f32 "
        "{%0,%1,%2,%3},{%4,%5,%6,%7},{%8,%9},{%0,%1,%2,%3};"
        : "+f"(c[0]), "+f"(c[1]), "+f"(c[2]), "+f"(c[3])
        : "r"(a[0]), "r"(a[1]), "r"(a[2]), "r"(a[3]), "r"(b[0]), "r"(b[1]));
}
// fp16 mma m16n8k16, fp16 accumulate (C/D packed half2 x2)
__device__ __forceinline__ void mma16h(unsigned* c, const unsigned* a, const unsigned* b) {
    asm volatile(
        "mma.sync.aligned.m16n8k16.row.col.f16.f16.f16.f16 "
        "{%0,%1},{%2,%3,%4,%5},{%6,%7},{%0,%1};"
        : "+r"(c[0]), "+r"(c[1])
        : "r"(a[0]), "r"(a[1]), "r"(a[2]), "r"(a[3]), "r"(b[0]), "r"(b[1]));
}

#define ST 72   /* smem row stride in halves = 144 bytes */

// ---------------- prep: x -> fp16 ----------------
__global__ __launch_bounds__(256) void cvt_x_kernel(
    const float* __restrict__ in, __half* __restrict__ out, int n4)
{
    int i = blockIdx.x * 256 + threadIdx.x;
    if (i < n4) {
        float4 v = ((const float4*)in)[i];
        uint2 o;
        o.x = h2pack(v.x, v.y);
        o.y = h2pack(v.z, v.w);
        ((uint2*)out)[i] = o;
    }
}

// ---------------- prep: transpose weights -> fp16  Wth[z][n][k] ----------------
__global__ __launch_bounds__(256) void cvt_wT_kernel(
    const float* __restrict__ w0, const float* __restrict__ w1,
    const float* __restrict__ w2, const float* __restrict__ w3,
    __half* __restrict__ out)
{
    __shared__ float t[32][33];
    const float* src = (blockIdx.z == 0) ? w0 : (blockIdx.z == 1) ? w1
                       : (blockIdx.z == 2) ? w2 : w3;
    __half* dst = out + (size_t)blockIdx.z * (size_t)D_MODEL * D_MODEL;
    int bx = blockIdx.x * 32;   // k tile
    int by = blockIdx.y * 32;   // n tile
#pragma unroll
    for (int j = 0; j < 4; j++)
        t[threadIdx.y + j * 8][threadIdx.x] =
            src[(size_t)(bx + threadIdx.y + j * 8) * D_MODEL + by + threadIdx.x];
    __syncthreads();
#pragma unroll
    for (int j = 0; j < 4; j++)
        dst[(size_t)(by + threadIdx.y + j * 8) * D_MODEL + bx + threadIdx.x] =
            __float2half_rn(t[threadIdx.x][threadIdx.y + j * 8]);
}

// ============================================================
// Kernel 1: MERGED QKV proj, fp16 m16n8k16 f32-acc (unchanged)
// ============================================================
#define GEMM_SMEM (4 * 128 * ST * 2)   /* 73728 bytes */

__global__ __launch_bounds__(256, 2) void proj_qkv_kernel(
    const __half* __restrict__ A, const __half* __restrict__ Wbase,
    const float* __restrict__ bq, const float* __restrict__ bk,
    const float* __restrict__ bv)
{
    extern __shared__ __half smh[];
    __half* Ah[2] = { smh, smh + 128 * ST };
    __half* Bh[2] = { smh + 2 * 128 * ST, smh + 3 * 128 * ST };

    const int z = blockIdx.z;
    const __half* W = Wbase + (size_t)z * D_MODEL * D_MODEL;
    const float* bias = (z == 0) ? bq : (z == 1) ? bk : bv;
    __half* out = QKVout16[z];

    const int tid = threadIdx.x;
    const int m0 = blockIdx.y * 128, n0 = blockIdx.x * 128;
    const int warp = tid >> 5, lane = tid & 31;
    const int g = lane >> 2, t = lane & 3;
    const int wm = (warp & 3) * 32, wn = (warp >> 2) * 64;

    float acc[2][8][4] = {};

#define PROJ_LOAD(buf, k0)                                                        \
    do {                                                                          \
        _Pragma("unroll")                                                         \
        for (int i = 0; i < 4; i++) {                                             \
            int id = tid + i * 256; int r = id >> 3, cc = id & 7;                 \
            cp16(su(&Ah[buf][r * ST + cc * 8]),                                   \
                 A + (size_t)(m0 + r) * 1024 + (k0) + cc * 8);                    \
        }                                                                         \
        _Pragma("unroll")                                                         \
        for (int i = 0; i < 4; i++) {                                             \
            int id = tid + i * 256; int r = id >> 3, cc = id & 7;                 \
            cp16(su(&Bh[buf][r * ST + cc * 8]),                                   \
                 W + (size_t)(n0 + r) * 1024 + (k0) + cc * 8);                    \
        }                                                                         \
        cpcommit();                                                               \
    } while (0)

    PROJ_LOAD(0, 0);
    for (int it = 0; it < 16; it++) {
        if (it + 1 < 16) { PROJ_LOAD((it + 1) & 1, (it + 1) * 64); cpwait1(); }
        else cpwait0();
        __syncthreads();
        const __half* a_s = Ah[it & 1];
        const __half* b_s = Bh[it & 1];
#pragma unroll
        for (int ks = 0; ks < 4; ks++) {
            unsigned a[2][4], b[8][2];
#pragma unroll
            for (int ma = 0; ma < 2; ma++) {
                int rb = wm + ma * 16;
                a[ma][0] = *(const unsigned*)&a_s[(rb + g) * ST + ks * 16 + 2 * t];
                a[ma][1] = *(const unsigned*)&a_s[(rb + g + 8) * ST + ks * 16 + 2 * t];
                a[ma][2] = *(const unsigned*)&a_s[(rb + g) * ST + ks * 16 + 2 * t + 8];
                a[ma][3] = *(const unsigned*)&a_s[(rb + g + 8) * ST + ks * 16 + 2 * t + 8];
            }
#pragma unroll
            for (int nb = 0; nb < 8; nb++) {
                int nr = wn + nb * 8 + g;
                b[nb][0] = *(const unsigned*)&b_s[nr * ST + ks * 16 + 2 * t];
                b[nb][1] = *(const unsigned*)&b_s[nr * ST + ks * 16 + 2 * t + 8];
            }
#pragma unroll
            for (int nb = 0; nb < 8; nb++)
#pragma unroll
                for (int ma = 0; ma < 2; ma++)
                    mma16(acc[ma][nb], a[ma], b[nb]);
        }
        __syncthreads();
    }

    const float scale = (z == 0) ? SCL_F : 1.0f;
#pragma unroll
    for (int ma = 0; ma < 2; ma++)
#pragma unroll
        for (int nb = 0; nb < 8; nb++) {
            int c0 = n0 + wn + nb * 8 + 2 * t;
            float b0 = __ldg(&bias[c0]), b1 = __ldg(&bias[c0 + 1]);
            int h = c0 >> 6, d = c0 & 63;
#pragma unroll
            for (int rr = 0; rr < 2; rr++) {
                int r = m0 + wm + ma * 16 + g + rr * 8;
                int bb = r >> 11, ss = r & 2047;
                float vx = (acc[ma][nb][rr * 2 + 0] + b0) * scale;
                float vy = (acc[ma][nb][rr * 2 + 1] + b1) * scale;
                if (z != 2) {
                    *(unsigned*)&out[(((size_t)(bb * 16 + h)) * 2048 + ss) * 64 + d] =
                        h2pack(vx, vy);
                } else {
                    __half* vb = out + (size_t)(bb * 16 + h) * 64 * 2048;
                    vb[(size_t)d * 2048 + ss]       = __float2half_rn(vx);
                    vb[(size_t)(d + 1) * 2048 + ss] = __float2half_rn(vy);
                }
            }
        }
}

// ============================================================
// Kernel 2: FLASH ATTENTION — S in fp16-accumulate mma
// ============================================================
#define FLASH_SMEM ((128 * ST + 4 * 64 * ST) * 2)   /* 55296 bytes */
#define ONES2 0x3C003C00u                            /* half2(1,1) */

__global__ __launch_bounds__(128, 2) void flash_attn_kernel()
{
    extern __shared__ __half smh[];
    __half* Qs = smh;                                    // 128 x ST
    __half* Ks[2] = { smh + 128 * ST, smh + 128 * ST + 64 * ST };
    __half* Vs[2] = { smh + 128 * ST + 2 * 64 * ST, smh + 128 * ST + 3 * 64 * ST };

    const int bh = blockIdx.y;
    const int m0 = blockIdx.x * 128;
    const __half* Qp = Qh + (size_t)bh * SEQ * DEPTH;
    const __half* Kp = Kh + (size_t)bh * SEQ * DEPTH;
    const __half* Vp = Vh + (size_t)bh * DEPTH * SEQ;   // [d][s]
    __half* Op = Oh + (size_t)bh * SEQ * DEPTH;

    const int tid = threadIdx.x;
    const int warp = tid >> 5, lane = tid & 31;
    const int g = lane >> 2, t = lane & 3;
    const int wq0 = warp * 32;
    const unsigned FULL = 0xffffffffu;

#pragma unroll
    for (int i = 0; i < 8; i++) {
        int id = tid + i * 128; int r = id >> 3, c = id & 7;
        cp16(su(&Qs[r * ST + c * 8]), Qp + (size_t)(m0 + r) * 64 + c * 8);
    }
    cpcommit();

#define KV_LOAD(buf, kv0)                                                         \
    do {                                                                          \
        _Pragma("unroll")                                                         \
        for (int i = 0; i < 4; i++) {                                             \
            int id = tid + i * 128; int r = id >> 3, c = id & 7;                  \
            cp16(su(&Ks[buf][r * ST + c * 8]),                                    \
                 Kp + (size_t)((kv0) + r) * 64 + c * 8);                          \
        }                                                                         \
        _Pragma("unroll")                                                         \
        for (int i = 0; i < 4; i++) {                                             \
            int id = tid + i * 128; int r = id >> 3, c = id & 7;                  \
            cp16(su(&Vs[buf][r * ST + c * 8]),                                    \
                 Vp + (size_t)r * 2048 + (kv0) + c * 8);                          \
        }                                                                         \
        cpcommit();                                                               \
    } while (0)

    KV_LOAD(0, 0);
    cpwait1();
    __syncthreads();

    // running max per ma: half2(lo = row g, hi = row g+8)
    __half2 mr2[2];
    mr2[0] = __float2half2_rn(-60000.f);
    mr2[1] = __float2half2_rn(-60000.f);

    // o[ma][0..7] = output cols; o[ma][8] = row-sum column (l), fp32 acc
    float o[2][9][4] = {};

    for (int j = 0; j < 32; j++) {
        if (j + 1 < 32) { KV_LOAD((j + 1) & 1, (j + 1) * 64); cpwait1(); }
        else cpwait0();
        __syncthreads();
        const __half* ks = Ks[j & 1];
        const __half* vs = Vs[j & 1];

        // ---- S = Q K^T : fp16 accumulate; C-frag IS the half2 pr layout ----
        // acc2[ma][nb][0] = half2(row g   cols 2t,2t+1)
        // acc2[ma][nb][1] = half2(row g+8 cols 2t,2t+1)
        unsigned acc2[2][8][2];
#pragma unroll
        for (int ma = 0; ma < 2; ma++)
#pragma unroll
            for (int nb = 0; nb < 8; nb++) {
                acc2[ma][nb][0] = 0u; acc2[ma][nb][1] = 0u;
            }

#pragma unroll
        for (int kb = 0; kb < 4; kb++) {
            unsigned a[2][4];
#pragma unroll
            for (int ma = 0; ma < 2; ma++) {
                int rb = wq0 + ma * 16;
                a[ma][0] = *(const unsigned*)&Qs[(rb + g) * ST + kb * 16 + 2 * t];
                a[ma][1] = *(const unsigned*)&Qs[(rb + g + 8) * ST + kb * 16 + 2 * t];
                a[ma][2] = *(const unsigned*)&Qs[(rb + g) * ST + kb * 16 + 2 * t + 8];
                a[ma][3] = *(const unsigned*)&Qs[(rb + g + 8) * ST + kb * 16 + 2 * t + 8];
            }
#pragma unroll
            for (int nb = 0; nb < 8; nb++) {
                unsigned b[2];
                int nr = nb * 8 + g;
                b[0] = *(const unsigned*)&ks[nr * ST + kb * 16 + 2 * t];
                b[1] = *(const unsigned*)&ks[nr * ST + kb * 16 + 2 * t + 8];
                mma16h(acc2[0][nb], a[0], b);
                mma16h(acc2[1][nb], a[1], b);
            }
        }

        // ---- max reduction in half2 domain (acc2 rows: [0]=row g, [1]=row g+8) ----
        float al[4];
#pragma unroll
        for (int ma = 0; ma < 2; ma++) {
            __half2 x0 = u2h(acc2[ma][0][0]), x1 = u2h(acc2[ma][0][1]);
#pragma unroll
            for (int nb = 1; nb < 8; nb++) {
                x0 = __hmax2(x0, u2h(acc2[ma][nb][0]));
                x1 = __hmax2(x1, u2h(acc2[ma][nb][1]));
            }
            __half2 mm = __halves2half2(
                __hmax(__low2half(x0), __high2half(x0)),
                __hmax(__low2half(x1), __high2half(x1)));
            mm = __hmax2(mm, u2h(__shfl_xor_sync(FULL, h2u(mm), 1)));
            mm = __hmax2(mm, u2h(__shfl_xor_sync(FULL, h2u(mm), 2)));
            __half2 nm = __hmax2(mr2[ma], mm);
            __half2 a2 = h2exp2(__hsub2(mr2[ma], nm));
            mr2[ma] = nm;
            al[ma * 2 + 0] = __low2float(a2);
            al[ma * 2 + 1] = __high2float(a2);
        }

        // ---- rescale O (incl. the l column) ----
#pragma unroll
        for (int ma = 0; ma < 2; ma++)
#pragma unroll
            for (int nb = 0; nb < 9; nb++) {
                o[ma][nb][0] *= al[ma * 2 + 0]; o[ma][nb][1] *= al[ma * 2 + 0];
                o[ma][nb][2] *= al[ma * 2 + 1]; o[ma][nb][3] *= al[ma * 2 + 1];
            }

        // ---- O += P @ V, P = exp2(acc2 - m) on the fly; nb==8 = ones col ----
#pragma unroll
        for (int kb = 0; kb < 4; kb++) {
            unsigned ap[2][4];
#pragma unroll
            for (int ma = 0; ma < 2; ma++) {
                __half2 m0b = __low2half2(mr2[ma]);
                __half2 m1b = __high2half2(mr2[ma]);
                ap[ma][0] = h2u(h2exp2(__hsub2(u2h(acc2[ma][2 * kb][0]),     m0b)));
                ap[ma][1] = h2u(h2exp2(__hsub2(u2h(acc2[ma][2 * kb][1]),     m1b)));
                ap[ma][2] = h2u(h2exp2(__hsub2(u2h(acc2[ma][2 * kb + 1][0]), m0b)));
                ap[ma][3] = h2u(h2exp2(__hsub2(u2h(acc2[ma][2 * kb + 1][1]), m1b)));
            }
#pragma unroll
            for (int nb = 0; nb < 9; nb++) {
                unsigned b[2];
                if (nb < 8) {
                    int nr = nb * 8 + g;
                    b[0] = *(const unsigned*)&vs[nr * ST + kb * 16 + 2 * t];
                    b[1] = *(const unsigned*)&vs[nr * ST + kb * 16 + 2 * t + 8];
                } else {
                    b[0] = ONES2; b[1] = ONES2;
                }
                mma16(o[0][nb], ap[0], b);
                mma16(o[1][nb], ap[1], b);
            }
        }
        __syncthreads();
    }

    // ---- epilogue: O /= l (from ones column), fp16 store ----
#pragma unroll
    for (int ma = 0; ma < 2; ma++) {
        float inv0 = 1.f / o[ma][8][0];
        float inv1 = 1.f / o[ma][8][2];
#pragma unroll
        for (int nb = 0; nb < 8; nb++) {
            int c0 = nb * 8 + 2 * t;
            {
                int r = m0 + wq0 + ma * 16 + g;
                *(unsigned*)&Op[(size_t)r * 64 + c0] =
                    h2pack(o[ma][nb][0] * inv0, o[ma][nb][1] * inv0);
            }
            {
                int r = m0 + wq0 + ma * 16 + g + 8;
                *(unsigned*)&Op[(size_t)r * 64 + c0] =
                    h2pack(o[ma][nb][2] * inv1, o[ma][nb][3] * inv1);
            }
        }
    }
}

// ============================================================
// Kernel 3: out = untranspose(Oh) @ wo + bo, fp16 mma, fp32 out
// ============================================================
__global__ __launch_bounds__(256, 2) void outproj_kernel(
    const __half* __restrict__ W, const float* __restrict__ bo,
    float* __restrict__ out)
{
    extern __shared__ __half smh[];
    __half* Ah[2] = { smh, smh + 128 * ST };
    __half* Bh[2] = { smh + 2 * 128 * ST, smh + 3 * 128 * ST };

    const int tid = threadIdx.x;
    const int m0 = blockIdx.y * 128, n0 = blockIdx.x * 128;
    const int warp = tid >> 5, lane = tid & 31;
    const int g = lane >> 2, t = lane & 3;
    const int wm = (warp & 3) * 32, wn = (warp >> 2) * 64;

    float acc[2][8][4] = {};

#define OP_LOAD(buf, k0)                                                          \
    do {                                                                          \
        _Pragma("unroll")                                                         \
        for (int i = 0; i < 4; i++) {                                             \
            int id = tid + i * 256; int r = id >> 3, cc = id & 7;                 \
            int m = m0 + r; int k = (k0) + cc * 8;                                \
            const __half* src = Oh + (((size_t)((m >> 11) * 16 + (k >> 6))) * 2048 \
                                      + (m & 2047)) * 64 + (k & 63);              \
            cp16(su(&Ah[buf][r * ST + cc * 8]), src);                             \
        }                                                                         \
        _Pragma("unroll")                                                         \
        for (int i = 0; i < 4; i++) {                                             \
            int id = tid + i * 256; int r = id >> 3, cc = id & 7;                 \
            cp16(su(&Bh[buf][r * ST + cc * 8]),                                   \
                 W + (size_t)(n0 + r) * 1024 + (k0) + cc * 8);                    \
        }                                                                         \
        cpcommit();                                                               \
    } while (0)

    OP_LOAD(0, 0);
    for (int it = 0; it < 16; it++) {
        if (it + 1 < 16) { OP_LOAD((it + 1) & 1, (it + 1) * 64); cpwait1(); }
        else cpwait0();
        __syncthreads();
        const __half* a_s = Ah[it & 1];
        const __half* b_s = Bh[it & 1];
#pragma unroll
        for (int ks = 0; ks < 4; ks++) {
            unsigned a[2][4], b[8][2];
#pragma unroll
            for (int ma = 0; ma < 2; ma++) {
                int rb = wm + ma * 16;
                a[ma][0] = *(const unsigned*)&a_s[(rb + g) * ST + ks * 16 + 2 * t];
                a[ma][1] = *(const unsigned*)&a_s[(rb + g + 8) * ST + ks * 16 + 2 * t];
                a[ma][2] = *(const unsigned*)&a_s[(rb + g) * ST + ks * 16 + 2 * t + 8];
                a[ma][3] = *(const unsigned*)&a_s[(rb + g + 8) * ST + ks * 16 + 2 * t + 8];
            }
#pragma unroll
            for (int nb = 0; nb < 8; nb++) {
                int nr = wn + nb * 8 + g;
                b[nb][0] = *(const unsigned*)&b_s[nr * ST + ks * 16 + 2 * t];
                b[nb][1] = *(const unsigned*)&b_s[nr * ST + ks * 16 + 2 * t + 8];
            }
#pragma unroll
            for (int nb = 0; nb < 8; nb++)
#pragma unroll
                for (int ma = 0; ma < 2; ma++)
                    mma16(acc[ma][nb], a[ma], b[nb]);
        }
        __syncthreads();
    }

#pragma unroll
    for (int ma = 0; ma < 2; ma++)
#pragma unroll
        for (int nb = 0; nb < 8; nb++) {
            int c0 = n0 + wn + nb * 8 + 2 * t;
            float b0 = __ldg(&bo[c0]), b1 = __ldg(&bo[c0 + 1]);
#pragma unroll
            for (int rr = 0; rr < 2; rr++) {
                int r = m0 + wm + ma * 16 + g + rr * 8;
                float2 v;
                v.x = acc[ma][nb][rr * 2 + 0] + b0;
                v.y = acc[ma][nb][rr * 2 + 1] + b1;
                *(float2*)&out[(size_t)r * 1024 + c0] = v;
            }
        }
}

// ============================================================
extern "C" void kernel_launch(void* const* d_in, const int* in_sizes, int n_in,
                              void* d_out, int out_size)
{
    const float* x  = (const float*)d_in[0];
    const float* wq = (const float*)d_in[1];
    const float* bq = (const float*)d_in[2];
    const float* wk = (const float*)d_in[3];
    const float* bk = (const float*)d_in[4];
    const float* wv = (const float*)d_in[5];
    const float* bv = (const float*)d_in[6];
    const float* wo = (const float*)d_in[7];
    const float* bo = (const float*)d_in[8];
    float* out = (float*)d_out;

    cudaFuncSetAttribute(proj_qkv_kernel,   cudaFuncAttributeMaxDynamicSharedMemorySize, GEMM_SMEM);
    cudaFuncSetAttribute(flash_attn_kernel, cudaFuncAttributeMaxDynamicSharedMemorySize, FLASH_SMEM);
    cudaFuncSetAttribute(outproj_kernel,    cudaFuncAttributeMaxDynamicSharedMemorySize, GEMM_SMEM);

    __half* Xh_p;  cudaGetSymbolAddress((void**)&Xh_p, Xh);
    __half* Wt_p;  cudaGetSymbolAddress((void**)&Wt_p, Wth);
    __half* Qp;    cudaGetSymbolAddress((void**)&Qp, Qh);
    __half* Kp;    cudaGetSymbolAddress((void**)&Kp, Kh);
    __half* Vp;    cudaGetSymbolAddress((void**)&Vp, Vh);

    static __half* h_tab[3];
    h_tab[0] = Qp; h_tab[1] = Kp; h_tab[2] = Vp;
    void* tab_dev; cudaGetSymbolAddress(&tab_dev, QKVout16);
    cudaMemcpyAsync(tab_dev, h_tab, sizeof(h_tab), cudaMemcpyHostToDevice);

    dim3 blk(256);
    const size_t WSZ = (size_t)D_MODEL * D_MODEL;

    {
        int n4 = (MROWS * D_MODEL) / 4;
        cvt_x_kernel<<<(n4 + 255) / 256, blk>>>(x, Xh_p, n4);
        cvt_wT_kernel<<<dim3(32, 32, 4), dim3(32, 8)>>>(wq, wk, wv, wo, Wt_p);
    }

    dim3 gqkv(D_MODEL / 128, MROWS / 128, 3);
    proj_qkv_kernel<<<gqkv, blk, GEMM_SMEM>>>(Xh_p, Wt_p, bq, bk, bv);

    flash_attn_kernel<<<dim3(SEQ / 128, BH), dim3(128), FLASH_SMEM>>>();

    outproj_kernel<<<dim3(D_MODEL / 128, MROWS / 128), blk, GEMM_SMEM>>>(
        Wt_p + 3 * WSZ, bo, out);
}